// round 1
// baseline (speedup 1.0000x reference)
#include <cuda_runtime.h>
#include <math.h>

#define Bsz   1024
#define Pn    20
#define Ln    3
#define Tn    5
#define En    128
#define Nseq  (Bsz*Pn)      /* 20480 */
#define NPL   (Bsz*Pn*Ln)   /* 61440 */
#define NREL  60
#define DDOC  768
#define DENT  100

// ---------------- scratch (global memory via __device__ arrays) ----------------
__device__ float g_news [2*Bsz*En];     // compressed news: rows 0..1023 = news1, 1024..2047 = news2
__device__ float g_relC [NREL*En];      // tanh-compressed relations
__device__ float g_nodeE[NPL*En];       // tanh-compressed path entities
__device__ float g_WTnode[128*512];     // W_ih[:, 0:128]^T, gate-packed: [k][j][g], g in {i,f,g,o}
__device__ float g_WTrel [128*512];     // W_ih[:, 128:256]^T, gate-packed
__device__ float g_WThh  [128*512];     // W_hh^T, gate-packed
__device__ float g_relGb [NREL*512];    // relC @ WTrel + (b_ih+b_hh), gate-packed
__device__ float g_newsG [2*Bsz*512];   // news  @ WTnode, gate-packed
__device__ float g_nodeG [NPL*512];     // nodeE @ WTnode, gate-packed

__device__ __forceinline__ float sigf(float x) { return 1.0f / (1.0f + expf(-x)); }

// ---------------- K0: transpose + gate-pack the LSTM weights ----------------
__global__ void k_transpose(const float* __restrict__ W_ih, const float* __restrict__ W_hh) {
    int idx = blockIdx.x * blockDim.x + threadIdx.x;
    if (idx >= 128 * 512) return;
    int k = idx >> 9;          // 0..127
    int c = idx & 511;         // packed col
    int j = c >> 2;            // h-col 0..127
    int g = c & 3;             // gate 0..3 (i,f,g,o)
    int row = g * 128 + j;     // torch gate row
    g_WTnode[idx] = W_ih[row * 256 + k];
    g_WTrel [idx] = W_ih[row * 256 + 128 + k];
    g_WThh  [idx] = W_hh[row * 128 + k];
}

// ---------------- K1: news compress (8 rows / block, 128 threads) ----------------
__global__ void k_news(const int* __restrict__ item1, const int* __restrict__ item2,
                       const float* __restrict__ doc_table,
                       const float* __restrict__ W1, const float* __restrict__ b1,
                       const float* __restrict__ W2, const float* __restrict__ b2) {
    __shared__ float ds[8 * DDOC];   // 24KB
    __shared__ float h1[8 * En];     // 4KB
    __shared__ int   items[8];
    int r0 = blockIdx.x * 8;
    int tid = threadIdx.x;
    if (tid < 8) {
        int row = r0 + tid;
        items[tid] = (row < Bsz) ? item1[row] : item2[row - Bsz];
    }
    __syncthreads();
    for (int idx = tid; idx < 8 * DDOC; idx += 128) {
        int r = idx / DDOC, k = idx % DDOC;
        ds[idx] = doc_table[(size_t)items[r] * DDOC + k];
    }
    __syncthreads();
    // phase 1: h1 = elu(doc @ W1 + b1)
    float a[8];
    float bb = b1[tid];
#pragma unroll
    for (int r = 0; r < 8; r++) a[r] = bb;
    for (int k = 0; k < DDOC; k++) {
        float w = W1[k * En + tid];
#pragma unroll
        for (int r = 0; r < 8; r++) a[r] += ds[r * DDOC + k] * w;
    }
#pragma unroll
    for (int r = 0; r < 8; r++) {
        float v = a[r];
        h1[r * En + tid] = (v > 0.0f) ? v : expm1f(v);
    }
    __syncthreads();
    // phase 2: out = tanh(h1 @ W2 + b2)
    float bb2 = b2[tid];
#pragma unroll
    for (int r = 0; r < 8; r++) a[r] = bb2;
    for (int k = 0; k < En; k++) {
        float w = W2[k * En + tid];
#pragma unroll
        for (int r = 0; r < 8; r++) a[r] += h1[r * En + k] * w;
    }
#pragma unroll
    for (int r = 0; r < 8; r++) g_news[(size_t)(r0 + r) * En + tid] = tanhf(a[r]);
}

// ---------------- K2: relation compress (60 blocks) ----------------
__global__ void k_relc(const float* __restrict__ rel_table,
                       const float* __restrict__ W, const float* __restrict__ b) {
    __shared__ float rr[DENT];
    int row = blockIdx.x;
    int tid = threadIdx.x;
    for (int k = tid; k < DENT; k += 128) rr[k] = rel_table[row * DENT + k];
    __syncthreads();
    float s = b[tid];
    for (int k = 0; k < DENT; k++) s += rr[k] * W[k * En + tid];
    g_relC[row * En + tid] = tanhf(s);
}

// ---------------- K2b: relGb = relC @ WTrel + (b_ih+b_hh)  (gate-packed) ----------------
__global__ void k_relg(const float* __restrict__ b_ih, const float* __restrict__ b_hh) {
    __shared__ float rc[En];
    int row = blockIdx.x;
    int c = threadIdx.x;          // 512 threads
    if (c < En) rc[c] = g_relC[row * En + c];
    __syncthreads();
    int j = c >> 2, g = c & 3;
    int gidx = g * 128 + j;
    float s = b_ih[gidx] + b_hh[gidx];
    for (int k = 0; k < En; k++) s += rc[k] * g_WTrel[k * 512 + c];
    g_relGb[row * 512 + c] = s;
}

// ---------------- K3: node entity compress (16 rows / block) ----------------
__global__ void k_node(const int* __restrict__ paths, const float* __restrict__ ent_table,
                       const float* __restrict__ W, const float* __restrict__ b) {
    __shared__ float es[16 * DENT];
    int r0 = blockIdx.x * 16;
    int tid = threadIdx.x;
    for (int idx = tid; idx < 16 * DENT; idx += 128) {
        int r = idx / DENT, k = idx % DENT;
        es[idx] = ent_table[(size_t)paths[r0 + r] * DENT + k];
    }
    __syncthreads();
    float acc[16];
    float bb = b[tid];
#pragma unroll
    for (int r = 0; r < 16; r++) acc[r] = bb;
    for (int k = 0; k < DENT; k++) {
        float w = W[k * En + tid];
#pragma unroll
        for (int r = 0; r < 16; r++) acc[r] += es[r * DENT + k] * w;
    }
#pragma unroll
    for (int r = 0; r < 16; r++) g_nodeE[(size_t)(r0 + r) * En + tid] = tanhf(acc[r]);
}

// ---------------- K4: C[M][512] = A[M][128] @ WT[128][512] (gate-packed WT) ----------------
__global__ __launch_bounds__(512, 1) void k_gemm128(const float* __restrict__ A,
                                                    const float* __restrict__ WT,
                                                    float* __restrict__ C) {
    __shared__ float As[128 * 65];    // [k][n], padded
    int n0 = blockIdx.x * 64;
    int tid = threadIdx.x;
    for (int idx = tid; idx < 64 * 128; idx += 512) {
        int ni = idx >> 7, k = idx & 127;
        As[k * 65 + ni] = A[(size_t)(n0 + ni) * 128 + k];
    }
    __syncthreads();
    int w = tid >> 5, l = tid & 31;
    int q  = (w & 3) * 32 + l;      // packed col group 0..127 -> cols q*4..q*4+3
    int nb = (w >> 2) * 16;
    float4 acc[16];
#pragma unroll
    for (int r = 0; r < 16; r++) acc[r] = make_float4(0.f, 0.f, 0.f, 0.f);
    for (int k = 0; k < 128; k++) {
        float4 wv = *(const float4*)(WT + k * 512 + q * 4);
#pragma unroll
        for (int r = 0; r < 16; r++) {
            float hv = As[k * 65 + nb + r];
            acc[r].x += hv * wv.x;
            acc[r].y += hv * wv.y;
            acc[r].z += hv * wv.z;
            acc[r].w += hv * wv.w;
        }
    }
#pragma unroll
    for (int r = 0; r < 16; r++)
        *(float4*)(C + (size_t)(n0 + nb + r) * 512 + q * 4) = acc[r];
}

// ---------------- K5: fused LSTM (5 steps) + MLP + score ----------------
__global__ __launch_bounds__(512, 1) void k_lstm(const int* __restrict__ edges,
                                                 const float* __restrict__ mlp_W1,
                                                 const float* __restrict__ mlp_b1,
                                                 const float* __restrict__ mlp_W2,
                                                 const float* __restrict__ mlp_b2,
                                                 float* __restrict__ scores_out) {
    __shared__ float hs[128 * 65];   // [hcol][n]
    __shared__ float part[64 * 4];
    int n0 = blockIdx.x * 64;
    int tid = threadIdx.x, w = tid >> 5, l = tid & 31;
    int j  = (w & 3) * 32 + l;      // this thread's h-column
    int nb = (w >> 2) * 16;
    float c[16];
#pragma unroll
    for (int r = 0; r < 16; r++) c[r] = 0.0f;

    for (int t = 0; t < Tn; t++) {
        float4 acc[16];
#pragma unroll
        for (int r = 0; r < 16; r++) acc[r] = make_float4(0.f, 0.f, 0.f, 0.f);
        if (t > 0) {
            for (int k = 0; k < 128; k++) {
                float4 wv = *(const float4*)(g_WThh + k * 512 + j * 4);
#pragma unroll
                for (int r = 0; r < 16; r++) {
                    float hv = hs[k * 65 + nb + r];
                    acc[r].x += hv * wv.x;
                    acc[r].y += hv * wv.y;
                    acc[r].z += hv * wv.z;
                    acc[r].w += hv * wv.w;
                }
            }
        }
        __syncthreads();   // all reads of hs done (or hs unused at t=0)
#pragma unroll
        for (int r = 0; r < 16; r++) {
            int n = n0 + nb + r;
            const float* bp;
            if (t == 0)      bp = g_newsG + (size_t)(n / Pn) * 512;
            else if (t == 4) bp = g_newsG + (size_t)(Bsz + n / Pn) * 512;
            else             bp = g_nodeG + (size_t)(n * Ln + (t - 1)) * 512;
            float4 b4 = *(const float4*)(bp + j * 4);
            int e = (t < Ln) ? edges[n * Ln + t] : 0;
            float4 r4 = *(const float4*)(g_relGb + e * 512 + j * 4);
            float gi = acc[r].x + b4.x + r4.x;
            float gf = acc[r].y + b4.y + r4.y;
            float gg = acc[r].z + b4.z + r4.z;
            float go = acc[r].w + b4.w + r4.w;
            c[r] = sigf(gf) * c[r] + sigf(gi) * tanhf(gg);
            float h = sigf(go) * tanhf(c[r]);
            hs[j * 65 + nb + r] = h;
        }
        __syncthreads();   // hs fully updated for next step
    }

    // MLP: m1 = relu(h @ W1 + b1); score = m1 @ W2 + b2
    float m1[16];
    float bb = mlp_b1[j];
#pragma unroll
    for (int r = 0; r < 16; r++) m1[r] = bb;
    for (int k = 0; k < 128; k++) {
        float w1 = mlp_W1[k * En + j];
#pragma unroll
        for (int r = 0; r < 16; r++) m1[r] += hs[k * 65 + nb + r] * w1;
    }
    float w2 = mlp_W2[j];
#pragma unroll
    for (int r = 0; r < 16; r++) {
        float v = fmaxf(m1[r], 0.0f) * w2;
#pragma unroll
        for (int off = 16; off > 0; off >>= 1) v += __shfl_xor_sync(0xffffffffu, v, off);
        if (l == 0) part[(nb + r) * 4 + (w & 3)] = v;
    }
    __syncthreads();
    if (tid < 64) {
        float s = part[tid * 4] + part[tid * 4 + 1] + part[tid * 4 + 2] + part[tid * 4 + 3]
                + mlp_b2[0];
        scores_out[n0 + tid] = s;
    }
}

// ---------------- K7: logsumexp -> predicts, BCE -> loss ----------------
__global__ void k_final(const float* __restrict__ label, float* __restrict__ out) {
    __shared__ float red[Bsz];
    int b = threadIdx.x;
    const float* sc = out + 1 + Bsz + b * Pn;
    float m = -1e30f;
#pragma unroll
    for (int p = 0; p < Pn; p++) m = fmaxf(m, sc[p] * 0.5f);
    float s = 0.0f;
#pragma unroll
    for (int p = 0; p < Pn; p++) s += expf(sc[p] * 0.5f - m);
    float lse = m + logf(s);
    float pr = 1.0f / (1.0f + expf(-lse));
    out[1 + b] = pr;
    float pc = fminf(fmaxf(pr, 1e-7f), 1.0f - 1e-7f);
    float lb = label[b];
    red[b] = -(lb * logf(pc) + (1.0f - lb) * logf(1.0f - pc));
    __syncthreads();
    for (int st = Bsz / 2; st > 0; st >>= 1) {
        if (b < st) red[b] += red[b + st];
        __syncthreads();
    }
    if (b == 0) out[0] = red[0] / (float)Bsz;
}

// ---------------- launch ----------------
extern "C" void kernel_launch(void* const* d_in, const int* in_sizes, int n_in,
                              void* d_out, int out_size) {
    const int*   item1     = (const int*)d_in[0];
    const int*   item2     = (const int*)d_in[1];
    const int*   paths     = (const int*)d_in[2];
    const int*   edges     = (const int*)d_in[3];
    const float* label     = (const float*)d_in[4];
    const float* doc_table = (const float*)d_in[5];
    const float* ent_table = (const float*)d_in[6];
    const float* rel_table = (const float*)d_in[7];
    const float* nc_W1 = (const float*)d_in[8];
    const float* nc_b1 = (const float*)d_in[9];
    const float* nc_W2 = (const float*)d_in[10];
    const float* nc_b2 = (const float*)d_in[11];
    const float* ec_W  = (const float*)d_in[12];
    const float* ec_b  = (const float*)d_in[13];
    const float* rc_W  = (const float*)d_in[14];
    const float* rc_b  = (const float*)d_in[15];
    const float* W_ih  = (const float*)d_in[16];
    const float* W_hh  = (const float*)d_in[17];
    const float* b_ih  = (const float*)d_in[18];
    const float* b_hh  = (const float*)d_in[19];
    const float* mlp_W1 = (const float*)d_in[20];
    const float* mlp_b1 = (const float*)d_in[21];
    const float* mlp_W2 = (const float*)d_in[22];
    const float* mlp_b2 = (const float*)d_in[23];
    float* out = (float*)d_out;

    float *p_news, *p_nodeE, *p_newsG, *p_nodeG;
    cudaGetSymbolAddress((void**)&p_news,  g_news);
    cudaGetSymbolAddress((void**)&p_nodeE, g_nodeE);
    cudaGetSymbolAddress((void**)&p_newsG, g_newsG);
    cudaGetSymbolAddress((void**)&p_nodeG, g_nodeG);
    float *p_WTnode;
    cudaGetSymbolAddress((void**)&p_WTnode, g_WTnode);

    // weight transposes (gate-packed)
    k_transpose<<<(128 * 512 + 511) / 512, 512>>>(W_ih, W_hh);
    // embedding compressions
    k_news<<<2 * Bsz / 8, 128>>>(item1, item2, doc_table, nc_W1, nc_b1, nc_W2, nc_b2);
    k_relc<<<NREL, 128>>>(rel_table, rc_W, rc_b);
    k_relg<<<NREL, 512>>>(b_ih, b_hh);
    k_node<<<NPL / 16, 128>>>(paths, ent_table, ec_W, ec_b);
    // input-gate GEMMs (node part of W_ih)
    k_gemm128<<<2 * Bsz / 64, 512>>>(p_news, p_WTnode, p_newsG);
    k_gemm128<<<NPL / 64, 512>>>(p_nodeE, p_WTnode, p_nodeG);
    // fused LSTM + MLP -> scores written directly into d_out[1+B ...]
    k_lstm<<<Nseq / 64, 512>>>(edges, mlp_W1, mlp_b1, mlp_W2, mlp_b2, out + 1 + Bsz);
    // predicts + loss
    k_final<<<1, Bsz>>>(label, out);
}

// round 2
// speedup vs baseline: 1.3749x; 1.3749x over previous
#include <cuda_runtime.h>
#include <math.h>

typedef unsigned long long u64;

#define Bsz   1024
#define Pn    20
#define Ln    3
#define Tn    5
#define En    128
#define Nseq  (Bsz*Pn)      /* 20480 */
#define NPL   (Bsz*Pn*Ln)   /* 61440 */
#define NREL  60
#define DDOC  768
#define DENT  100

// ---------------- scratch ----------------
__device__ float g_news [2*Bsz*En];
__device__ float g_relC [NREL*En];
__device__ float g_nodeE[NPL*En];
__device__ float g_WTnode[128*512];     // W_ih[:,0:128]^T gate-packed [k][j][g]
__device__ float g_WTrel [128*512];
__device__ float g_WThh  [128*512];
__device__ float g_relGb [NREL*512];
__device__ float g_newsG [2*Bsz*512];
__device__ float g_nodeG [NPL*512];

__device__ __forceinline__ float sigf(float x) { return 1.0f / (1.0f + expf(-x)); }

// packed f32x2 helpers (FFMA2)
__device__ __forceinline__ u64 ffma2(u64 a, u64 b, u64 c) {
    u64 d;
    asm("fma.rn.f32x2 %0, %1, %2, %3;" : "=l"(d) : "l"(a), "l"(b), "l"(c));
    return d;
}
__device__ __forceinline__ u64 dup2(float x) {
    u64 d;
    unsigned xi = __float_as_uint(x);
    asm("mov.b64 %0, {%1, %1};" : "=l"(d) : "r"(xi));
    return d;
}
__device__ __forceinline__ float2 up2(u64 v) {
    unsigned lo, hi;
    asm("mov.b64 {%0, %1}, %2;" : "=r"(lo), "=r"(hi) : "l"(v));
    return make_float2(__uint_as_float(lo), __uint_as_float(hi));
}

// ---------------- K0: transpose + gate-pack ----------------
__global__ void k_transpose(const float* __restrict__ W_ih, const float* __restrict__ W_hh) {
    int idx = blockIdx.x * blockDim.x + threadIdx.x;
    if (idx >= 128 * 512) return;
    int k = idx >> 9;
    int c = idx & 511;
    int j = c >> 2;
    int g = c & 3;
    int row = g * 128 + j;
    g_WTnode[idx] = W_ih[row * 256 + k];
    g_WTrel [idx] = W_ih[row * 256 + 128 + k];
    g_WThh  [idx] = W_hh[row * 128 + k];
}

// ---------------- K1: news compress ----------------
__global__ void k_news(const int* __restrict__ item1, const int* __restrict__ item2,
                       const float* __restrict__ doc_table,
                       const float* __restrict__ W1, const float* __restrict__ b1,
                       const float* __restrict__ W2, const float* __restrict__ b2) {
    __shared__ float ds[8 * DDOC];
    __shared__ float h1[8 * En];
    __shared__ int   items[8];
    int r0 = blockIdx.x * 8;
    int tid = threadIdx.x;
    if (tid < 8) {
        int row = r0 + tid;
        items[tid] = (row < Bsz) ? item1[row] : item2[row - Bsz];
    }
    __syncthreads();
    for (int idx = tid; idx < 8 * DDOC; idx += 128) {
        int r = idx / DDOC, k = idx % DDOC;
        ds[idx] = doc_table[(size_t)items[r] * DDOC + k];
    }
    __syncthreads();
    float a[8];
    float bb = b1[tid];
#pragma unroll
    for (int r = 0; r < 8; r++) a[r] = bb;
    for (int k = 0; k < DDOC; k++) {
        float w = W1[k * En + tid];
#pragma unroll
        for (int r = 0; r < 8; r++) a[r] += ds[r * DDOC + k] * w;
    }
#pragma unroll
    for (int r = 0; r < 8; r++) {
        float v = a[r];
        h1[r * En + tid] = (v > 0.0f) ? v : expm1f(v);
    }
    __syncthreads();
    float bb2 = b2[tid];
#pragma unroll
    for (int r = 0; r < 8; r++) a[r] = bb2;
    for (int k = 0; k < En; k++) {
        float w = W2[k * En + tid];
#pragma unroll
        for (int r = 0; r < 8; r++) a[r] += h1[r * En + k] * w;
    }
#pragma unroll
    for (int r = 0; r < 8; r++) g_news[(size_t)(r0 + r) * En + tid] = tanhf(a[r]);
}

// ---------------- K2: relation compress ----------------
__global__ void k_relc(const float* __restrict__ rel_table,
                       const float* __restrict__ W, const float* __restrict__ b) {
    __shared__ float rr[DENT];
    int row = blockIdx.x;
    int tid = threadIdx.x;
    for (int k = tid; k < DENT; k += 128) rr[k] = rel_table[row * DENT + k];
    __syncthreads();
    float s = b[tid];
    for (int k = 0; k < DENT; k++) s += rr[k] * W[k * En + tid];
    g_relC[row * En + tid] = tanhf(s);
}

// ---------------- K2b: relGb ----------------
__global__ void k_relg(const float* __restrict__ b_ih, const float* __restrict__ b_hh) {
    __shared__ float rc[En];
    int row = blockIdx.x;
    int c = threadIdx.x;
    if (c < En) rc[c] = g_relC[row * En + c];
    __syncthreads();
    int j = c >> 2, g = c & 3;
    int gidx = g * 128 + j;
    float s = b_ih[gidx] + b_hh[gidx];
    for (int k = 0; k < En; k++) s += rc[k] * g_WTrel[k * 512 + c];
    g_relGb[row * 512 + c] = s;
}

// ---------------- K3: node entity compress (16 rows/block, f32x2) ----------------
__global__ void k_node(const int* __restrict__ paths, const float* __restrict__ ent_table,
                       const float* __restrict__ W, const float* __restrict__ b) {
    __shared__ __align__(16) float es[DENT * 18];   // [k][r], stride 18 (even, low-conflict)
    int r0 = blockIdx.x * 16;
    int tid = threadIdx.x;
    for (int idx = tid; idx < 16 * DENT; idx += 128) {
        int r = idx / DENT, k = idx - r * DENT;
        es[k * 18 + r] = ent_table[(size_t)paths[r0 + r] * DENT + k];
    }
    __syncthreads();
    u64 acc2[8];
    u64 bd = dup2(b[tid]);
#pragma unroll
    for (int p = 0; p < 8; p++) acc2[p] = bd;
    for (int k = 0; k < DENT; k++) {
        u64 wd = dup2(W[k * En + tid]);
        const u64* hp = (const u64*)&es[k * 18];
#pragma unroll
        for (int p = 0; p < 8; p++) acc2[p] = ffma2(hp[p], wd, acc2[p]);
    }
#pragma unroll
    for (int p = 0; p < 8; p++) {
        float2 a = up2(acc2[p]);
        g_nodeE[(size_t)(r0 + 2 * p)     * En + tid] = tanhf(a.x);
        g_nodeE[(size_t)(r0 + 2 * p + 1) * En + tid] = tanhf(a.y);
    }
}

// ---------------- K4: C[M][512] = A[M][128] @ WT[128][512] (f32x2 row-pairs) ----------------
__global__ __launch_bounds__(512, 1) void k_gemm128(const float* __restrict__ A,
                                                    const float* __restrict__ WT,
                                                    float* __restrict__ C) {
    __shared__ __align__(16) float As[128 * 66];    // [k][n], stride 66 (8B-aligned pairs)
    int n0 = blockIdx.x * 64;
    int tid = threadIdx.x;
    for (int idx = tid; idx < 64 * 128; idx += 512) {
        int ni = idx >> 7, k = idx & 127;
        As[k * 66 + ni] = A[(size_t)(n0 + ni) * 128 + k];
    }
    __syncthreads();
    int w = tid >> 5, l = tid & 31;
    int q  = (w & 3) * 32 + l;      // packed col group (4 floats)
    int nb = (w >> 2) * 16;         // 16 rows = 8 pairs
    u64 acc[8][4];
#pragma unroll
    for (int p = 0; p < 8; p++)
#pragma unroll
        for (int cI = 0; cI < 4; cI++) acc[p][cI] = 0ull;

    for (int k = 0; k < 128; k++) {
        float4 wv = *(const float4*)(WT + k * 512 + q * 4);
        u64 w0 = dup2(wv.x), w1 = dup2(wv.y), w2 = dup2(wv.z), w3 = dup2(wv.w);
        const u64* hp = (const u64*)&As[k * 66 + nb];
#pragma unroll
        for (int p = 0; p < 8; p++) {
            u64 hv = hp[p];
            acc[p][0] = ffma2(hv, w0, acc[p][0]);
            acc[p][1] = ffma2(hv, w1, acc[p][1]);
            acc[p][2] = ffma2(hv, w2, acc[p][2]);
            acc[p][3] = ffma2(hv, w3, acc[p][3]);
        }
    }
#pragma unroll
    for (int p = 0; p < 8; p++) {
        float2 a0 = up2(acc[p][0]), a1 = up2(acc[p][1]);
        float2 a2 = up2(acc[p][2]), a3 = up2(acc[p][3]);
        *(float4*)(C + (size_t)(n0 + nb + 2 * p)     * 512 + q * 4) =
            make_float4(a0.x, a1.x, a2.x, a3.x);
        *(float4*)(C + (size_t)(n0 + nb + 2 * p + 1) * 512 + q * 4) =
            make_float4(a0.y, a1.y, a2.y, a3.y);
    }
}

// ---------------- K5: fused LSTM + MLP + score (f32x2) ----------------
#define LSTM_ROW(r, GI, GF, GG, GO) do {                                        \
    int n = n0 + nb + (r);                                                      \
    const float* bp;                                                            \
    if (t == 0)      bp = g_newsG + (size_t)(n / Pn) * 512;                     \
    else if (t == 4) bp = g_newsG + (size_t)(Bsz + n / Pn) * 512;               \
    else             bp = g_nodeG + (size_t)(n * Ln + (t - 1)) * 512;           \
    float4 b4 = *(const float4*)(bp + j * 4);                                   \
    int e = (t < Ln) ? edges[n * Ln + t] : 0;                                   \
    float4 r4 = *(const float4*)(g_relGb + e * 512 + j * 4);                    \
    float gi = (GI) + b4.x + r4.x;                                              \
    float gf = (GF) + b4.y + r4.y;                                              \
    float gg = (GG) + b4.z + r4.z;                                              \
    float go = (GO) + b4.w + r4.w;                                              \
    c[(r)] = sigf(gf) * c[(r)] + sigf(gi) * tanhf(gg);                          \
    hs[j * 66 + nb + (r)] = sigf(go) * tanhf(c[(r)]);                           \
} while (0)

__global__ __launch_bounds__(512, 1) void k_lstm(const int* __restrict__ edges,
                                                 const float* __restrict__ mlp_W1,
                                                 const float* __restrict__ mlp_b1,
                                                 const float* __restrict__ mlp_W2,
                                                 const float* __restrict__ mlp_b2,
                                                 float* __restrict__ scores_out) {
    __shared__ __align__(16) float hs[128 * 66];   // [hcol][n]
    __shared__ float part[64 * 4];
    int n0 = blockIdx.x * 64;
    int tid = threadIdx.x, w = tid >> 5, l = tid & 31;
    int j  = (w & 3) * 32 + l;
    int nb = (w >> 2) * 16;
    float c[16];
#pragma unroll
    for (int r = 0; r < 16; r++) c[r] = 0.0f;

    for (int t = 0; t < Tn; t++) {
        u64 acc[8][4];
#pragma unroll
        for (int p = 0; p < 8; p++)
#pragma unroll
            for (int cI = 0; cI < 4; cI++) acc[p][cI] = 0ull;
        if (t > 0) {
            for (int k = 0; k < 128; k++) {
                float4 wv = *(const float4*)(g_WThh + k * 512 + j * 4);
                u64 w0 = dup2(wv.x), w1 = dup2(wv.y), w2 = dup2(wv.z), w3 = dup2(wv.w);
                const u64* hp = (const u64*)&hs[k * 66 + nb];
#pragma unroll
                for (int p = 0; p < 8; p++) {
                    u64 hv = hp[p];
                    acc[p][0] = ffma2(hv, w0, acc[p][0]);
                    acc[p][1] = ffma2(hv, w1, acc[p][1]);
                    acc[p][2] = ffma2(hv, w2, acc[p][2]);
                    acc[p][3] = ffma2(hv, w3, acc[p][3]);
                }
            }
        }
        __syncthreads();   // all reads of hs done
#pragma unroll
        for (int p = 0; p < 8; p++) {
            float2 a0 = up2(acc[p][0]), a1 = up2(acc[p][1]);
            float2 a2 = up2(acc[p][2]), a3 = up2(acc[p][3]);
            LSTM_ROW(2 * p,     a0.x, a1.x, a2.x, a3.x);
            LSTM_ROW(2 * p + 1, a0.y, a1.y, a2.y, a3.y);
        }
        __syncthreads();   // hs fully updated
    }

    // MLP: m1 = relu(h @ W1 + b1); score = m1 @ W2 + b2
    u64 m2[8];
    u64 bbd = dup2(mlp_b1[j]);
#pragma unroll
    for (int p = 0; p < 8; p++) m2[p] = bbd;
    for (int k = 0; k < 128; k++) {
        u64 wd = dup2(mlp_W1[k * En + j]);
        const u64* hp = (const u64*)&hs[k * 66 + nb];
#pragma unroll
        for (int p = 0; p < 8; p++) m2[p] = ffma2(hp[p], wd, m2[p]);
    }
    float m1[16];
#pragma unroll
    for (int p = 0; p < 8; p++) {
        float2 a = up2(m2[p]);
        m1[2 * p] = a.x; m1[2 * p + 1] = a.y;
    }
    float w2v = mlp_W2[j];
#pragma unroll
    for (int r = 0; r < 16; r++) {
        float v = fmaxf(m1[r], 0.0f) * w2v;
#pragma unroll
        for (int off = 16; off > 0; off >>= 1) v += __shfl_xor_sync(0xffffffffu, v, off);
        if (l == 0) part[(nb + r) * 4 + (w & 3)] = v;
    }
    __syncthreads();
    if (tid < 64) {
        float s = part[tid * 4] + part[tid * 4 + 1] + part[tid * 4 + 2] + part[tid * 4 + 3]
                + mlp_b2[0];
        scores_out[n0 + tid] = s;
    }
}

// ---------------- K7: logsumexp + BCE ----------------
__global__ void k_final(const float* __restrict__ label, float* __restrict__ out) {
    __shared__ float red[Bsz];
    int b = threadIdx.x;
    const float* sc = out + 1 + Bsz + b * Pn;
    float m = -1e30f;
#pragma unroll
    for (int p = 0; p < Pn; p++) m = fmaxf(m, sc[p] * 0.5f);
    float s = 0.0f;
#pragma unroll
    for (int p = 0; p < Pn; p++) s += expf(sc[p] * 0.5f - m);
    float lse = m + logf(s);
    float pr = 1.0f / (1.0f + expf(-lse));
    out[1 + b] = pr;
    float pc = fminf(fmaxf(pr, 1e-7f), 1.0f - 1e-7f);
    float lb = label[b];
    red[b] = -(lb * logf(pc) + (1.0f - lb) * logf(1.0f - pc));
    __syncthreads();
    for (int st = Bsz / 2; st > 0; st >>= 1) {
        if (b < st) red[b] += red[b + st];
        __syncthreads();
    }
    if (b == 0) out[0] = red[0] / (float)Bsz;
}

// ---------------- launch ----------------
extern "C" void kernel_launch(void* const* d_in, const int* in_sizes, int n_in,
                              void* d_out, int out_size) {
    const int*   item1     = (const int*)d_in[0];
    const int*   item2     = (const int*)d_in[1];
    const int*   paths     = (const int*)d_in[2];
    const int*   edges     = (const int*)d_in[3];
    const float* label     = (const float*)d_in[4];
    const float* doc_table = (const float*)d_in[5];
    const float* ent_table = (const float*)d_in[6];
    const float* rel_table = (const float*)d_in[7];
    const float* nc_W1 = (const float*)d_in[8];
    const float* nc_b1 = (const float*)d_in[9];
    const float* nc_W2 = (const float*)d_in[10];
    const float* nc_b2 = (const float*)d_in[11];
    const float* ec_W  = (const float*)d_in[12];
    const float* ec_b  = (const float*)d_in[13];
    const float* rc_W  = (const float*)d_in[14];
    const float* rc_b  = (const float*)d_in[15];
    const float* W_ih  = (const float*)d_in[16];
    const float* W_hh  = (const float*)d_in[17];
    const float* b_ih  = (const float*)d_in[18];
    const float* b_hh  = (const float*)d_in[19];
    const float* mlp_W1 = (const float*)d_in[20];
    const float* mlp_b1 = (const float*)d_in[21];
    const float* mlp_W2 = (const float*)d_in[22];
    const float* mlp_b2 = (const float*)d_in[23];
    float* out = (float*)d_out;

    float *p_news, *p_nodeE, *p_newsG, *p_nodeG, *p_WTnode;
    cudaGetSymbolAddress((void**)&p_news,  g_news);
    cudaGetSymbolAddress((void**)&p_nodeE, g_nodeE);
    cudaGetSymbolAddress((void**)&p_newsG, g_newsG);
    cudaGetSymbolAddress((void**)&p_nodeG, g_nodeG);
    cudaGetSymbolAddress((void**)&p_WTnode, g_WTnode);

    k_transpose<<<(128 * 512 + 511) / 512, 512>>>(W_ih, W_hh);
    k_news<<<2 * Bsz / 8, 128>>>(item1, item2, doc_table, nc_W1, nc_b1, nc_W2, nc_b2);
    k_relc<<<NREL, 128>>>(rel_table, rc_W, rc_b);
    k_relg<<<NREL, 512>>>(b_ih, b_hh);
    k_node<<<NPL / 16, 128>>>(paths, ent_table, ec_W, ec_b);
    k_gemm128<<<2 * Bsz / 64, 512>>>(p_news, p_WTnode, p_newsG);
    k_gemm128<<<NPL / 64, 512>>>(p_nodeE, p_WTnode, p_nodeG);
    k_lstm<<<Nseq / 64, 512>>>(edges, mlp_W1, mlp_b1, mlp_W2, mlp_b2, out + 1 + Bsz);
    k_final<<<1, Bsz>>>(label, out);
}

// round 4
// speedup vs baseline: 2.6193x; 1.9051x over previous
#include <cuda_runtime.h>
#include <cuda_fp16.h>
#include <math.h>
#include <stdint.h>

typedef unsigned long long u64;

#define Bsz   1024
#define Pn    20
#define Ln    3
#define Tn    5
#define En    128
#define Nseq  (Bsz*Pn)          /* 20480 */
#define NPL   (Bsz*Pn*Ln)       /* 61440 */
#define NREL  60
#define DDOC  768
#define DENT  100
#define MTOT  (NPL + 2*Bsz)     /* 63488 = 496*128 */

// ---------------- device scratch ----------------
__device__ __half g_AE [(size_t)MTOT * 128];    // f16 A matrix rows (nodes, then news1, news2)
__device__ __half g_Bn [512 * 128];             // f16 W_ih[:,0:128] quad-packed: row c=j*4+g, col k
__device__ __half g_Bh [512 * 128];             // f16 W_hh quad-packed
__device__ float  g_WTrel[128 * 512];           // f32 [k][c]
__device__ float  g_relC [NREL * En];
__device__ float  g_relGb[NREL * 512];          // relC@WTrel + (b_ih+b_hh), quad-packed
__device__ float  g_G    [(size_t)MTOT * 512];  // input-gate preacts, quad-packed f32

__device__ __forceinline__ float sigf(float x) { return 1.0f / (1.0f + expf(-x)); }

// ---- f32x2 helpers ----
__device__ __forceinline__ u64 ffma2(u64 a, u64 b, u64 c) {
    u64 d; asm("fma.rn.f32x2 %0, %1, %2, %3;" : "=l"(d) : "l"(a), "l"(b), "l"(c)); return d;
}
__device__ __forceinline__ u64 dup2(float x) {
    u64 d; unsigned xi = __float_as_uint(x);
    asm("mov.b64 %0, {%1, %1};" : "=l"(d) : "r"(xi)); return d;
}
__device__ __forceinline__ u64 pack2(float lo, float hi) {
    u64 d; asm("mov.b64 %0, {%1, %2};" : "=l"(d) : "r"(__float_as_uint(lo)), "r"(__float_as_uint(hi)));
    return d;
}
__device__ __forceinline__ float2 up2(u64 v) {
    unsigned lo, hi; asm("mov.b64 {%0, %1}, %2;" : "=r"(lo), "=r"(hi) : "l"(v));
    return make_float2(__uint_as_float(lo), __uint_as_float(hi));
}

// ---- mma / ldmatrix helpers (family-safe PTX, sm_80+) ----
__device__ __forceinline__ uint32_t s2u(const void* p) {
    uint32_t a;
    asm("{ .reg .u64 t; cvta.to.shared.u64 t, %1; cvt.u32.u64 %0, t; }" : "=r"(a) : "l"(p));
    return a;
}
__device__ __forceinline__ void ldmA(uint32_t* r, uint32_t addr) {
    asm volatile("ldmatrix.sync.aligned.m8n8.x4.shared.b16 {%0,%1,%2,%3}, [%4];"
                 : "=r"(r[0]), "=r"(r[1]), "=r"(r[2]), "=r"(r[3]) : "r"(addr));
}
__device__ __forceinline__ void ldmB(uint32_t* r, uint32_t addr) {
    asm volatile("ldmatrix.sync.aligned.m8n8.x2.shared.b16 {%0,%1}, [%2];"
                 : "=r"(r[0]), "=r"(r[1]) : "r"(addr));
}
__device__ __forceinline__ void mma16816(float* d, const uint32_t* a, const uint32_t* b) {
    asm volatile("mma.sync.aligned.m16n8k16.row.col.f32.f16.f16.f32 "
        "{%0,%1,%2,%3}, {%4,%5,%6,%7}, {%8,%9}, {%0,%1,%2,%3};"
        : "+f"(d[0]), "+f"(d[1]), "+f"(d[2]), "+f"(d[3])
        : "r"(a[0]), "r"(a[1]), "r"(a[2]), "r"(a[3]), "r"(b[0]), "r"(b[1]));
}

#define ASTR 272   /* smem row stride in bytes (136 halves): banks shift 4/row -> conflict-free */

// ---------------- K0: transpose + pack weights ----------------
__global__ void k_transpose(const float* __restrict__ W_ih, const float* __restrict__ W_hh) {
    int idx = blockIdx.x * blockDim.x + threadIdx.x;
    if (idx >= 512 * 128) return;
    int c = idx >> 7, k = idx & 127;
    int row = (c & 3) * 128 + (c >> 2);
    g_Bn[c * 128 + k] = __float2half_rn(W_ih[row * 256 + k]);
    g_Bh[c * 128 + k] = __float2half_rn(W_hh[row * 128 + k]);
    g_WTrel[k * 512 + c] = W_ih[row * 256 + 128 + k];
}

// ---------------- K1: news compress -> f16 rows ----------------
__global__ void k_news(const int* __restrict__ item1, const int* __restrict__ item2,
                       const float* __restrict__ doc_table,
                       const float* __restrict__ W1, const float* __restrict__ b1,
                       const float* __restrict__ W2, const float* __restrict__ b2) {
    __shared__ float ds[8 * DDOC];
    __shared__ float h1[8 * En];
    __shared__ int   items[8];
    int r0 = blockIdx.x * 8;
    int tid = threadIdx.x;
    if (tid < 8) {
        int row = r0 + tid;
        items[tid] = (row < Bsz) ? item1[row] : item2[row - Bsz];
    }
    __syncthreads();
    for (int idx = tid; idx < 8 * DDOC; idx += 128) {
        int r = idx / DDOC, k = idx % DDOC;
        ds[idx] = doc_table[(size_t)items[r] * DDOC + k];
    }
    __syncthreads();
    float a[8];
    float bb = b1[tid];
#pragma unroll
    for (int r = 0; r < 8; r++) a[r] = bb;
    for (int k = 0; k < DDOC; k++) {
        float w = W1[k * En + tid];
#pragma unroll
        for (int r = 0; r < 8; r++) a[r] += ds[r * DDOC + k] * w;
    }
#pragma unroll
    for (int r = 0; r < 8; r++) {
        float v = a[r];
        h1[r * En + tid] = (v > 0.0f) ? v : expm1f(v);
    }
    __syncthreads();
    float bb2 = b2[tid];
#pragma unroll
    for (int r = 0; r < 8; r++) a[r] = bb2;
    for (int k = 0; k < En; k++) {
        float w = W2[k * En + tid];
#pragma unroll
        for (int r = 0; r < 8; r++) a[r] += h1[r * En + k] * w;
    }
#pragma unroll
    for (int r = 0; r < 8; r++)
        g_AE[(size_t)(NPL + r0 + r) * En + tid] = __float2half_rn(tanhf(a[r]));
}

// ---------------- K2: relation compress ----------------
__global__ void k_relc(const float* __restrict__ rel_table,
                       const float* __restrict__ W, const float* __restrict__ b) {
    __shared__ float rr[DENT];
    int row = blockIdx.x;
    int tid = threadIdx.x;
    for (int k = tid; k < DENT; k += 128) rr[k] = rel_table[row * DENT + k];
    __syncthreads();
    float s = b[tid];
    for (int k = 0; k < DENT; k++) s += rr[k] * W[k * En + tid];
    g_relC[row * En + tid] = tanhf(s);
}

// ---------------- K2b: relGb = relC @ WTrel + (b_ih+b_hh) ----------------
__global__ void k_relg(const float* __restrict__ b_ih, const float* __restrict__ b_hh) {
    __shared__ float rc[En];
    int row = blockIdx.x;
    int c = threadIdx.x;
    if (c < En) rc[c] = g_relC[row * En + c];
    __syncthreads();
    int j = c >> 2, g = c & 3;
    int gidx = g * 128 + j;
    float s = b_ih[gidx] + b_hh[gidx];
    for (int k = 0; k < En; k++) s += rc[k] * g_WTrel[k * 512 + c];
    g_relGb[row * 512 + c] = s;
}

// ---------------- K3: node entity compress -> f16 rows (f32x2 math) ----------------
__global__ void k_node(const int* __restrict__ paths, const float* __restrict__ ent_table,
                       const float* __restrict__ W, const float* __restrict__ b) {
    __shared__ __align__(16) float es[DENT * 18];
    int r0 = blockIdx.x * 16;
    int tid = threadIdx.x;
    for (int idx = tid; idx < 16 * DENT; idx += 128) {
        int r = idx / DENT, k = idx - r * DENT;
        es[k * 18 + r] = ent_table[(size_t)paths[r0 + r] * DENT + k];
    }
    __syncthreads();
    u64 acc2[8];
    u64 bd = dup2(b[tid]);
#pragma unroll
    for (int p = 0; p < 8; p++) acc2[p] = bd;
    for (int k = 0; k < DENT; k++) {
        u64 wd = dup2(W[k * En + tid]);
        const u64* hp = (const u64*)&es[k * 18];
#pragma unroll
        for (int p = 0; p < 8; p++) acc2[p] = ffma2(hp[p], wd, acc2[p]);
    }
#pragma unroll
    for (int p = 0; p < 8; p++) {
        float2 a = up2(acc2[p]);
        g_AE[(size_t)(r0 + 2 * p)     * En + tid] = __float2half_rn(tanhf(a.x));
        g_AE[(size_t)(r0 + 2 * p + 1) * En + tid] = __float2half_rn(tanhf(a.y));
    }
}

// ---------------- K4: HMMA GEMM  g_G = g_AE(f16) @ g_Bn(f16)^T ----------------
// block: 128 rows x 256 cols; 16 warps = 4(m) x 4(n); warp = 32 rows x 64 cols
#define SMG_A 0
#define SMG_B (128 * ASTR)                /* 34816 */
#define SMG_TOTAL (SMG_B + 256 * ASTR)    /* 104448 */
__global__ __launch_bounds__(512, 1) void k_gemm_mma() {
    extern __shared__ char sm[];
    int tid = threadIdx.x, w = tid >> 5, l = tid & 31;
    int wm = w & 3, wn = w >> 2;
    int row0 = blockIdx.x * 128;
    int n0b  = blockIdx.y * 256;

    // stage A (128 rows x 256B) and B (256 rows x 256B) with ASTR padding
    const uint4* Ag = (const uint4*)g_AE;
    for (int idx = tid; idx < 128 * 16; idx += 512) {
        int r = idx >> 4, c4 = idx & 15;
        *(uint4*)(sm + SMG_A + r * ASTR + c4 * 16) = Ag[(size_t)(row0 + r) * 16 + c4];
    }
    const uint4* Bg = (const uint4*)g_Bn;
    for (int idx = tid; idx < 256 * 16; idx += 512) {
        int n = idx >> 4, c4 = idx & 15;
        *(uint4*)(sm + SMG_B + n * ASTR + c4 * 16) = Bg[(size_t)(n0b + n) * 16 + c4];
    }
    __syncthreads();

    uint32_t base = s2u(sm);
    int g8 = l & 7;
    uint32_t aBase = base + SMG_A + (uint32_t)(wm * 32 + g8 + ((l >> 3) & 1) * 8) * ASTR
                   + ((l >> 4) & 1) * 16;
    uint32_t bBase = base + SMG_B + (uint32_t)(wn * 64 + g8) * ASTR + ((l >> 3) & 1) * 16;

    float acc[2][8][4];
#pragma unroll
    for (int mt = 0; mt < 2; mt++)
#pragma unroll
        for (int nt = 0; nt < 8; nt++)
#pragma unroll
            for (int q = 0; q < 4; q++) acc[mt][nt][q] = 0.0f;

#pragma unroll
    for (int kt = 0; kt < 8; kt++) {
        uint32_t a[2][4];
        ldmA(a[0], aBase + kt * 32);
        ldmA(a[1], aBase + 16 * ASTR + kt * 32);
#pragma unroll
        for (int nt = 0; nt < 8; nt++) {
            uint32_t b[2];
            ldmB(b, bBase + nt * 8 * ASTR + kt * 32);
            mma16816(acc[0][nt], a[0], b);
            mma16816(acc[1][nt], a[1], b);
        }
    }

    int tg = l & 3, gg = l >> 2;
#pragma unroll
    for (int mt = 0; mt < 2; mt++) {
        int r = row0 + wm * 32 + mt * 16 + gg;
#pragma unroll
        for (int nt = 0; nt < 8; nt++) {
            int cc = n0b + wn * 64 + nt * 8 + 2 * tg;
            *(float2*)(g_G + (size_t)r * 512 + cc) =
                make_float2(acc[mt][nt][0], acc[mt][nt][1]);
            *(float2*)(g_G + (size_t)(r + 8) * 512 + cc) =
                make_float2(acc[mt][nt][2], acc[mt][nt][3]);
        }
    }
}

// ---------------- K5: HMMA LSTM + fused MLP ----------------
// block: 64 seqs; 16 warps = 4(m:16 rows) x 4(n:128 cols)
#define SML_A0 0
#define SML_A1 (64 * ASTR)                 /* 17408 */
#define SML_B  (2 * 64 * ASTR)             /* 34816 */
#define SML_W1 SML_B                       /* overlay after last mma */
#define SML_PART (SML_B + 512 * ASTR)      /* 174080 */
#define SML_TOTAL (SML_PART + 2048)        /* 176128 */
__global__ __launch_bounds__(512, 1) void k_lstm_mma(const int* __restrict__ edges,
                                                     const float* __restrict__ mlp_W1,
                                                     const float* __restrict__ mlp_b1,
                                                     const float* __restrict__ mlp_W2,
                                                     const float* __restrict__ mlp_b2,
                                                     float* __restrict__ scores_out) {
    extern __shared__ char sm[];
    int tid = threadIdx.x, w = tid >> 5, l = tid & 31;
    int wm = w & 3, wn = w >> 2;
    int n0 = blockIdx.x * 64;
    int g8 = l & 7, tg = l & 3, gg = l >> 2;
    int odd = tg & 1;

    // stage B = Whh (512 rows x 256B)
    const uint4* Bg = (const uint4*)g_Bh;
    for (int idx = tid; idx < 512 * 16; idx += 512) {
        int n = idx >> 4, c4 = idx & 15;
        *(uint4*)(sm + SML_B + n * ASTR + c4 * 16) = Bg[(size_t)n * 16 + c4];
    }
    __syncthreads();

    uint32_t base = s2u(sm);
    uint32_t aLane = (uint32_t)(wm * 16 + g8 + ((l >> 3) & 1) * 8) * ASTR + ((l >> 4) & 1) * 16;
    uint32_t bBase = base + SML_B + (uint32_t)(wn * 128 + g8) * ASTR + ((l >> 3) & 1) * 16;

    // this thread's fixed (row, seq)
    int r_loc = wm * 16 + gg + odd * 8;
    int seq = n0 + r_loc;
    int bIdx = seq / Pn;

    float cst[16];
#pragma unroll
    for (int q = 0; q < 16; q++) cst[q] = 0.0f;

    for (int t = 0; t < Tn; t++) {
        uint32_t aRd = base + ((t & 1) ? SML_A0 : SML_A1) + aLane;  // read h(t-1) buffer
        char* hWr = sm + ((t & 1) ? SML_A1 : SML_A0);               // write h(t) buffer
        int rowG = (t == 0) ? NPL + bIdx
                 : (t == 4) ? NPL + Bsz + bIdx
                 : seq * Ln + (t - 1);
        int e = (t < Ln) ? edges[seq * Ln + t] : 0;
        const float* gp = g_G + (size_t)rowG * 512;
        const float* rp = g_relGb + e * 512;

#pragma unroll
        for (int half = 0; half < 2; half++) {
            float acc[8][4];
#pragma unroll
            for (int nt = 0; nt < 8; nt++)
#pragma unroll
                for (int q = 0; q < 4; q++) acc[nt][q] = 0.0f;
            if (t > 0) {
#pragma unroll
                for (int kt = 0; kt < 8; kt++) {
                    uint32_t a[4];
                    ldmA(a, aRd + kt * 32);
#pragma unroll
                    for (int ntl = 0; ntl < 8; ntl++) {
                        uint32_t b[2];
                        ldmB(b, bBase + (half * 8 + ntl) * 8 * ASTR + kt * 32);
                        mma16816(acc[ntl], a, b);
                    }
                }
            }
#pragma unroll
            for (int ntl = 0; ntl < 8; ntl++) {
                int nt = half * 8 + ntl;
                float d0 = acc[ntl][0], d1 = acc[ntl][1];
                float d2 = acc[ntl][2], d3 = acc[ntl][3];
                float x0 = __shfl_xor_sync(0xffffffffu, d0, 1);
                float x1 = __shfl_xor_sync(0xffffffffu, d1, 1);
                float x2 = __shfl_xor_sync(0xffffffffu, d2, 1);
                float x3 = __shfl_xor_sync(0xffffffffu, d3, 1);
                float gi = odd ? x2 : d0;
                float gf = odd ? x3 : d1;
                float gG = odd ? d2 : x0;
                float gO = odd ? d3 : x1;
                int q = wn * 32 + nt * 2 + (tg >> 1);
                float4 g4 = *(const float4*)(gp + q * 4);
                float4 r4 = *(const float4*)(rp + q * 4);
                gi += g4.x + r4.x;
                gf += g4.y + r4.y;
                gG += g4.z + r4.z;
                gO += g4.w + r4.w;
                cst[nt] = sigf(gf) * cst[nt] + sigf(gi) * tanhf(gG);
                float hv = sigf(gO) * tanhf(cst[nt]);
                *(__half*)(hWr + r_loc * ASTR + q * 2) = __float2half_rn(hv);
            }
        }
        __syncthreads();
    }

    // ---- fused MLP: h final is in buffer A0 ----
    float* sW1 = (float*)(sm + SML_W1);
    for (int idx = tid; idx < 128 * 128; idx += 512) sW1[idx] = mlp_W1[idx];
    __syncthreads();

    int m = tid & 63, jb = (tid >> 6) * 16;
    u64 m1[8];
#pragma unroll
    for (int p = 0; p < 8; p++) m1[p] = pack2(mlp_b1[jb + 2 * p], mlp_b1[jb + 2 * p + 1]);
    const __half* hrow = (const __half*)(sm + SML_A0 + m * ASTR);
#pragma unroll 4
    for (int k = 0; k < 128; k++) {
        u64 hd = dup2(__half2float(hrow[k]));
        const u64* wp = (const u64*)&sW1[k * 128 + jb];
#pragma unroll
        for (int p = 0; p < 8; p++) m1[p] = ffma2(wp[p], hd, m1[p]);
    }
    float v = 0.0f;
#pragma unroll
    for (int p = 0; p < 8; p++) {
        float2 a = up2(m1[p]);
        v += fmaxf(a.x, 0.0f) * mlp_W2[jb + 2 * p]
           + fmaxf(a.y, 0.0f) * mlp_W2[jb + 2 * p + 1];
    }
    float* part = (float*)(sm + SML_PART);
    part[m * 8 + (tid >> 6)] = v;
    __syncthreads();
    if (tid < 64) {
        float s = mlp_b2[0];
#pragma unroll
        for (int p = 0; p < 8; p++) s += part[tid * 8 + p];
        scores_out[n0 + tid] = s;
    }
}

// ---------------- K7: logsumexp + BCE ----------------
__global__ void k_final(const float* __restrict__ label, float* __restrict__ out) {
    __shared__ float red[Bsz];
    int b = threadIdx.x;
    const float* sc = out + 1 + Bsz + b * Pn;
    float mx = -1e30f;
#pragma unroll
    for (int p = 0; p < Pn; p++) mx = fmaxf(mx, sc[p] * 0.5f);
    float s = 0.0f;
#pragma unroll
    for (int p = 0; p < Pn; p++) s += expf(sc[p] * 0.5f - mx);
    float lse = mx + logf(s);
    float pr = 1.0f / (1.0f + expf(-lse));
    out[1 + b] = pr;
    float pc = fminf(fmaxf(pr, 1e-7f), 1.0f - 1e-7f);
    float lb = label[b];
    red[b] = -(lb * logf(pc) + (1.0f - lb) * logf(1.0f - pc));
    __syncthreads();
    for (int st = Bsz / 2; st > 0; st >>= 1) {
        if (b < st) red[b] += red[b + st];
        __syncthreads();
    }
    if (b == 0) out[0] = red[0] / (float)Bsz;
}

// ---------------- launch ----------------
extern "C" void kernel_launch(void* const* d_in, const int* in_sizes, int n_in,
                              void* d_out, int out_size) {
    const int*   item1     = (const int*)d_in[0];
    const int*   item2     = (const int*)d_in[1];
    const int*   paths     = (const int*)d_in[2];
    const int*   edges     = (const int*)d_in[3];
    const float* label     = (const float*)d_in[4];
    const float* doc_table = (const float*)d_in[5];
    const float* ent_table = (const float*)d_in[6];
    const float* rel_table = (const float*)d_in[7];
    const float* nc_W1 = (const float*)d_in[8];
    const float* nc_b1 = (const float*)d_in[9];
    const float* nc_W2 = (const float*)d_in[10];
    const float* nc_b2 = (const float*)d_in[11];
    const float* ec_W  = (const float*)d_in[12];
    const float* ec_b  = (const float*)d_in[13];
    const float* rc_W  = (const float*)d_in[14];
    const float* rc_b  = (const float*)d_in[15];
    const float* W_ih  = (const float*)d_in[16];
    const float* W_hh  = (const float*)d_in[17];
    const float* b_ih  = (const float*)d_in[18];
    const float* b_hh  = (const float*)d_in[19];
    const float* mlp_W1 = (const float*)d_in[20];
    const float* mlp_b1 = (const float*)d_in[21];
    const float* mlp_W2 = (const float*)d_in[22];
    const float* mlp_b2 = (const float*)d_in[23];
    float* out = (float*)d_out;

    cudaFuncSetAttribute(k_gemm_mma, cudaFuncAttributeMaxDynamicSharedMemorySize, SMG_TOTAL);
    cudaFuncSetAttribute(k_lstm_mma, cudaFuncAttributeMaxDynamicSharedMemorySize, SML_TOTAL);

    k_transpose<<<(512 * 128 + 511) / 512, 512>>>(W_ih, W_hh);
    k_news<<<2 * Bsz / 8, 128>>>(item1, item2, doc_table, nc_W1, nc_b1, nc_W2, nc_b2);
    k_relc<<<NREL, 128>>>(rel_table, rc_W, rc_b);
    k_relg<<<NREL, 512>>>(b_ih, b_hh);
    k_node<<<NPL / 16, 128>>>(paths, ent_table, ec_W, ec_b);
    k_gemm_mma<<<dim3(MTOT / 128, 2), 512, SMG_TOTAL>>>();
    k_lstm_mma<<<Nseq / 64, 512, SML_TOTAL>>>(edges, mlp_W1, mlp_b1, mlp_W2, mlp_b2,
                                              out + 1 + Bsz);
    k_final<<<1, Bsz>>>(label, out);
}

// round 5
// speedup vs baseline: 2.6982x; 1.0301x over previous
#include <cuda_runtime.h>
#include <cuda_fp16.h>
#include <math.h>
#include <stdint.h>

typedef unsigned long long u64;

#define Bsz   1024
#define Pn    20
#define Ln    3
#define Tn    5
#define En    128
#define Nseq  (Bsz*Pn)          /* 20480 */
#define NPL   (Bsz*Pn*Ln)       /* 61440 */
#define NREL  60
#define DDOC  768
#define DENT  100
#define MTOT  (NPL + 2*Bsz)     /* 63488 = 496*128 */

// ---------------- device scratch ----------------
__device__ __half g_AE [(size_t)MTOT * 128];    // f16 A rows (nodes, then news1, news2)
__device__ __half g_Bn [512 * 128];             // f16 W_ih[:,0:128] quad-packed rows c=j*4+g
__device__ __half g_Bh [512 * 128];             // f16 W_hh quad-packed
__device__ float  g_WTrel[128 * 512];           // f32 [k][c]
__device__ float  g_relGb[NREL * 512];          // relC@WTrel + bias, PERMUTED quads, f32
__device__ __half g_G16 [(size_t)MTOT * 512];   // input-gate preacts, PERMUTED quads, f16

__device__ __forceinline__ float sigf(float x) { return 1.0f / (1.0f + expf(-x)); }

// ---- f32x2 helpers ----
__device__ __forceinline__ u64 ffma2(u64 a, u64 b, u64 c) {
    u64 d; asm("fma.rn.f32x2 %0, %1, %2, %3;" : "=l"(d) : "l"(a), "l"(b), "l"(c)); return d;
}
__device__ __forceinline__ u64 dup2(float x) {
    u64 d; unsigned xi = __float_as_uint(x);
    asm("mov.b64 %0, {%1, %1};" : "=l"(d) : "r"(xi)); return d;
}
__device__ __forceinline__ u64 pack2(float lo, float hi) {
    u64 d; asm("mov.b64 %0, {%1, %2};" : "=l"(d) : "r"(__float_as_uint(lo)), "r"(__float_as_uint(hi)));
    return d;
}
__device__ __forceinline__ float2 up2(u64 v) {
    unsigned lo, hi; asm("mov.b64 {%0, %1}, %2;" : "=r"(lo), "=r"(hi) : "l"(v));
    return make_float2(__uint_as_float(lo), __uint_as_float(hi));
}

// ---- mma / ldmatrix (family-safe PTX) ----
__device__ __forceinline__ uint32_t s2u(const void* p) {
    uint32_t a;
    asm("{ .reg .u64 t; cvta.to.shared.u64 t, %1; cvt.u32.u64 %0, t; }" : "=r"(a) : "l"(p));
    return a;
}
__device__ __forceinline__ void ldmA(uint32_t* r, uint32_t addr) {
    asm volatile("ldmatrix.sync.aligned.m8n8.x4.shared.b16 {%0,%1,%2,%3}, [%4];"
                 : "=r"(r[0]), "=r"(r[1]), "=r"(r[2]), "=r"(r[3]) : "r"(addr));
}
__device__ __forceinline__ void ldmB(uint32_t* r, uint32_t addr) {
    asm volatile("ldmatrix.sync.aligned.m8n8.x2.shared.b16 {%0,%1}, [%2];"
                 : "=r"(r[0]), "=r"(r[1]) : "r"(addr));
}
__device__ __forceinline__ void mma16816(float* d, const uint32_t* a, const uint32_t* b) {
    asm volatile("mma.sync.aligned.m16n8k16.row.col.f32.f16.f16.f32 "
        "{%0,%1,%2,%3}, {%4,%5,%6,%7}, {%8,%9}, {%0,%1,%2,%3};"
        : "+f"(d[0]), "+f"(d[1]), "+f"(d[2]), "+f"(d[3])
        : "r"(a[0]), "r"(a[1]), "r"(a[2]), "r"(a[3]), "r"(b[0]), "r"(b[1]));
}

#define ASTR 272   /* operand smem row stride (bytes) */
#define CSTR 528   /* C staging stride: 16B-aligned, bank shift 4/row */

// ---------------- K0: transpose + pack weights ----------------
__global__ void k_transpose(const float* __restrict__ W_ih, const float* __restrict__ W_hh) {
    int idx = blockIdx.x * blockDim.x + threadIdx.x;
    if (idx >= 512 * 128) return;
    int c = idx >> 7, k = idx & 127;
    int row = (c & 3) * 128 + (c >> 2);
    g_Bn[c * 128 + k] = __float2half_rn(W_ih[row * 256 + k]);
    g_Bh[c * 128 + k] = __float2half_rn(W_hh[row * 128 + k]);
    g_WTrel[k * 512 + c] = W_ih[row * 256 + 128 + k];
}

// ---------------- K1: news compress -> f16 rows ----------------
__global__ void k_news(const int* __restrict__ item1, const int* __restrict__ item2,
                       const float* __restrict__ doc_table,
                       const float* __restrict__ W1, const float* __restrict__ b1,
                       const float* __restrict__ W2, const float* __restrict__ b2) {
    __shared__ float ds[8 * DDOC];
    __shared__ float h1[8 * En];
    __shared__ int   items[8];
    int r0 = blockIdx.x * 8;
    int tid = threadIdx.x;
    if (tid < 8) {
        int row = r0 + tid;
        items[tid] = (row < Bsz) ? item1[row] : item2[row - Bsz];
    }
    __syncthreads();
    for (int idx = tid; idx < 8 * DDOC; idx += 128) {
        int r = idx / DDOC, k = idx % DDOC;
        ds[idx] = doc_table[(size_t)items[r] * DDOC + k];
    }
    __syncthreads();
    float a[8];
    float bb = b1[tid];
#pragma unroll
    for (int r = 0; r < 8; r++) a[r] = bb;
    for (int k = 0; k < DDOC; k++) {
        float w = W1[k * En + tid];
#pragma unroll
        for (int r = 0; r < 8; r++) a[r] += ds[r * DDOC + k] * w;
    }
#pragma unroll
    for (int r = 0; r < 8; r++) {
        float v = a[r];
        h1[r * En + tid] = (v > 0.0f) ? v : expm1f(v);
    }
    __syncthreads();
    float bb2 = b2[tid];
#pragma unroll
    for (int r = 0; r < 8; r++) a[r] = bb2;
    for (int k = 0; k < En; k++) {
        float w = W2[k * En + tid];
#pragma unroll
        for (int r = 0; r < 8; r++) a[r] += h1[r * En + k] * w;
    }
#pragma unroll
    for (int r = 0; r < 8; r++)
        g_AE[(size_t)(NPL + r0 + r) * En + tid] = __float2half_rn(tanhf(a[r]));
}

// ---------------- K2: relation compress + gate projection (merged, permuted out) ----------------
__global__ void k_rel(const float* __restrict__ rel_table,
                      const float* __restrict__ W, const float* __restrict__ b,
                      const float* __restrict__ b_ih, const float* __restrict__ b_hh) {
    __shared__ float rr[DENT];
    __shared__ float rc[En];
    int row = blockIdx.x, tid = threadIdx.x;
    if (tid < DENT) rr[tid] = rel_table[row * DENT + tid];
    __syncthreads();
    if (tid < En) {
        float s = b[tid];
        for (int k = 0; k < DENT; k++) s += rr[k] * W[k * En + tid];
        rc[tid] = tanhf(s);
    }
    __syncthreads();
    int c = tid;                       // 512 threads, one packed col each
    int j = c >> 2, g = c & 3;
    int gidx = g * 128 + j;
    float s = b_ih[gidx] + b_hh[gidx];
    for (int k = 0; k < En; k++) s += rc[k] * g_WTrel[k * 512 + c];
    int q = c >> 2;
    int p = (q & ~31) | ((q & 1) << 4) | ((q & 31) >> 1);
    g_relGb[row * 512 + p * 4 + g] = s;
}

// ---------------- K3: node entity compress -> f16 rows ----------------
__global__ void k_node(const int* __restrict__ paths, const float* __restrict__ ent_table,
                       const float* __restrict__ W, const float* __restrict__ b) {
    __shared__ __align__(16) float es[DENT * 18];
    int r0 = blockIdx.x * 16;
    int tid = threadIdx.x;
    for (int idx = tid; idx < 16 * DENT; idx += 128) {
        int r = idx / DENT, k = idx - r * DENT;
        es[k * 18 + r] = ent_table[(size_t)paths[r0 + r] * DENT + k];
    }
    __syncthreads();
    u64 acc2[8];
    u64 bd = dup2(b[tid]);
#pragma unroll
    for (int p = 0; p < 8; p++) acc2[p] = bd;
    for (int k = 0; k < DENT; k++) {
        u64 wd = dup2(W[k * En + tid]);
        const u64* hp = (const u64*)&es[k * 18];
#pragma unroll
        for (int p = 0; p < 8; p++) acc2[p] = ffma2(hp[p], wd, acc2[p]);
    }
#pragma unroll
    for (int p = 0; p < 8; p++) {
        float2 a = up2(acc2[p]);
        g_AE[(size_t)(r0 + 2 * p)     * En + tid] = __float2half_rn(tanhf(a.x));
        g_AE[(size_t)(r0 + 2 * p + 1) * En + tid] = __float2half_rn(tanhf(a.y));
    }
}

// ---------------- K4: HMMA GEMM  g_G16 = g_AE @ g_Bn^T (permuted fp16 out) ----------------
#define SMG_A 0
#define SMG_B (128 * ASTR)                /* 34816 */
#define SMG_TOTAL (SMG_B + 256 * ASTR)    /* 104448 */
__global__ __launch_bounds__(512, 1) void k_gemm_mma() {
    extern __shared__ char sm[];
    int tid = threadIdx.x, w = tid >> 5, l = tid & 31;
    int wm = w & 3, wn = w >> 2;
    int row0 = blockIdx.x * 128;
    int n0b  = blockIdx.y * 256;

    const uint4* Ag = (const uint4*)g_AE;
    for (int idx = tid; idx < 128 * 16; idx += 512) {
        int r = idx >> 4, c4 = idx & 15;
        *(uint4*)(sm + SMG_A + r * ASTR + c4 * 16) = Ag[(size_t)(row0 + r) * 16 + c4];
    }
    const uint4* Bg = (const uint4*)g_Bn;
    for (int idx = tid; idx < 256 * 16; idx += 512) {
        int n = idx >> 4, c4 = idx & 15;
        *(uint4*)(sm + SMG_B + n * ASTR + c4 * 16) = Bg[(size_t)(n0b + n) * 16 + c4];
    }
    __syncthreads();

    uint32_t base = s2u(sm);
    int g8 = l & 7;
    uint32_t aBase = base + SMG_A + (uint32_t)(wm * 32 + g8 + ((l >> 3) & 1) * 8) * ASTR
                   + ((l >> 4) & 1) * 16;
    uint32_t bBase = base + SMG_B + (uint32_t)(wn * 64 + g8) * ASTR + ((l >> 3) & 1) * 16;

    float acc[2][8][4];
#pragma unroll
    for (int mt = 0; mt < 2; mt++)
#pragma unroll
        for (int nt = 0; nt < 8; nt++)
#pragma unroll
            for (int q = 0; q < 4; q++) acc[mt][nt][q] = 0.0f;

#pragma unroll
    for (int kt = 0; kt < 8; kt++) {
        uint32_t a[2][4];
        ldmA(a[0], aBase + kt * 32);
        ldmA(a[1], aBase + 16 * ASTR + kt * 32);
#pragma unroll
        for (int nt = 0; nt < 8; nt++) {
            uint32_t b[2];
            ldmB(b, bBase + nt * 8 * ASTR + kt * 32);
            mma16816(acc[0][nt], a[0], b);
            mma16816(acc[1][nt], a[1], b);
        }
    }
    __syncthreads();   // all ldmatrix done; reuse smem as C staging

    // stage C as fp16, quad-permuted within the 64 local quads
    int tg = l & 3, gg = l >> 2;
#pragma unroll
    for (int mt = 0; mt < 2; mt++) {
        int r = wm * 32 + mt * 16 + gg;
#pragma unroll
        for (int nt = 0; nt < 8; nt++) {
            int qg = wn * 16 + nt * 2 + (tg >> 1);                         // local quad 0..63
            int pl = (qg & ~31) | ((qg & 1) << 4) | ((qg & 31) >> 1);
            *(__half2*)(sm + r * CSTR + pl * 8 + (tg & 1) * 4) =
                __floats2half2_rn(acc[mt][nt][0], acc[mt][nt][1]);
            *(__half2*)(sm + (r + 8) * CSTR + pl * 8 + (tg & 1) * 4) =
                __floats2half2_rn(acc[mt][nt][2], acc[mt][nt][3]);
        }
    }
    __syncthreads();
    // coalesced streamout: 128 rows x 512B
    for (int it = tid; it < 128 * 32; it += 512) {
        int r = it >> 5, bb = it & 31;
        uint4 v = *(uint4*)(sm + r * CSTR + bb * 16);
        *(uint4*)((char*)g_G16 + (size_t)(row0 + r) * 1024 + (size_t)n0b * 2 + bb * 16) = v;
    }
}

// ---------------- K5: HMMA LSTM + fused MLP ----------------
#define SML_A0 0
#define SML_A1 (64 * ASTR)                 /* 17408 */
#define SML_B  (2 * 64 * ASTR)             /* 34816 */
#define SML_W1 SML_B
#define SML_PART (SML_B + 512 * ASTR)      /* 174080 */
#define SML_TOTAL (SML_PART + 2048)
__global__ __launch_bounds__(512, 1) void k_lstm_mma(const int* __restrict__ edges,
                                                     const float* __restrict__ mlp_W1,
                                                     const float* __restrict__ mlp_b1,
                                                     const float* __restrict__ mlp_W2,
                                                     const float* __restrict__ mlp_b2,
                                                     float* __restrict__ scores_out) {
    extern __shared__ char sm[];
    int tid = threadIdx.x, w = tid >> 5, l = tid & 31;
    int wm = w & 3, wn = w >> 2;
    int n0 = blockIdx.x * 64;
    int g8 = l & 7, tg = l & 3, gg = l >> 2;
    int odd = tg & 1;            // fragment gate-pair parity
    int par = tg >> 1;           // quad parity (permutation key)

    const uint4* Bg = (const uint4*)g_Bh;
    for (int idx = tid; idx < 512 * 16; idx += 512) {
        int n = idx >> 4, c4 = idx & 15;
        *(uint4*)(sm + SML_B + n * ASTR + c4 * 16) = Bg[(size_t)n * 16 + c4];
    }
    __syncthreads();

    uint32_t base = s2u(sm);
    uint32_t aLane = (uint32_t)(wm * 16 + g8 + ((l >> 3) & 1) * 8) * ASTR + ((l >> 4) & 1) * 16;
    uint32_t bBase = base + SML_B + (uint32_t)(wn * 128 + g8) * ASTR + ((l >> 3) & 1) * 16;

    int r_loc = wm * 16 + gg + odd * 8;
    int seq = n0 + r_loc;
    int bIdx = seq / Pn;

    float cst[16];
#pragma unroll
    for (int q = 0; q < 16; q++) cst[q] = 0.0f;

    for (int t = 0; t < Tn; t++) {
        uint32_t aRd = base + ((t & 1) ? SML_A0 : SML_A1) + aLane;
        char* hWr = sm + ((t & 1) ? SML_A1 : SML_A0);
        int rowG = (t == 0) ? NPL + bIdx
                 : (t == 4) ? NPL + Bsz + bIdx
                 : seq * Ln + (t - 1);
        int e = (t < Ln) ? edges[seq * Ln + t] : 0;
        // lane's contiguous permuted gate stream (16 quads = 128B)
        const uint4* gp = (const uint4*)((const char*)g_G16 + (size_t)rowG * 1024
                                         + (size_t)(wn * 32 + par * 16) * 8);
        const float4* rp = (const float4*)(g_relGb + (size_t)e * 512
                                           + (wn * 32 + par * 16) * 4);

#pragma unroll
        for (int half = 0; half < 2; half++) {
            uint4 gu[4];
#pragma unroll
            for (int k2 = 0; k2 < 4; k2++) gu[k2] = gp[half * 4 + k2];

            float acc[8][4];
#pragma unroll
            for (int nt = 0; nt < 8; nt++)
#pragma unroll
                for (int q = 0; q < 4; q++) acc[nt][q] = 0.0f;
            if (t > 0) {
#pragma unroll
                for (int kt = 0; kt < 8; kt++) {
                    uint32_t a[4];
                    ldmA(a, aRd + kt * 32);
#pragma unroll
                    for (int ntl = 0; ntl < 8; ntl++) {
                        uint32_t b[2];
                        ldmB(b, bBase + (half * 8 + ntl) * 8 * ASTR + kt * 32);
                        mma16816(acc[ntl], a, b);
                    }
                }
            }
#pragma unroll
            for (int ntl = 0; ntl < 8; ntl++) {
                int nt = half * 8 + ntl;
                float d0 = acc[ntl][0], d1 = acc[ntl][1];
                float d2 = acc[ntl][2], d3 = acc[ntl][3];
                float x0 = __shfl_xor_sync(0xffffffffu, d0, 1);
                float x1 = __shfl_xor_sync(0xffffffffu, d1, 1);
                float x2 = __shfl_xor_sync(0xffffffffu, d2, 1);
                float x3 = __shfl_xor_sync(0xffffffffu, d3, 1);
                float gi = odd ? x2 : d0;
                float gf = odd ? x3 : d1;
                float gG = odd ? d2 : x0;
                float gO = odd ? d3 : x1;
                // gates from permuted fp16 stream: quad nt = gu[ntl>>1], half-pair ntl&1
                __half2 hif = ((const __half2*)&gu[ntl >> 1])[(ntl & 1) * 2 + 0];
                __half2 hgo = ((const __half2*)&gu[ntl >> 1])[(ntl & 1) * 2 + 1];
                float2 fif = __half22float2(hif);
                float2 fgo = __half22float2(hgo);
                float4 r4 = rp[nt];
                gi += fif.x + r4.x;
                gf += fif.y + r4.y;
                gG += fgo.x + r4.z;
                gO += fgo.y + r4.w;
                cst[nt] = sigf(gf) * cst[nt] + sigf(gi) * tanhf(gG);
                float hv = sigf(gO) * tanhf(cst[nt]);
                int q = wn * 32 + nt * 2 + par;     // UNPERMUTED h column
                *(__half*)(hWr + r_loc * ASTR + q * 2) = __float2half_rn(hv);
            }
        }
        __syncthreads();
    }

    // ---- fused MLP: final h in buffer A0 ----
    float* sW1 = (float*)(sm + SML_W1);
    for (int idx = tid; idx < 128 * 128; idx += 512) sW1[idx] = mlp_W1[idx];
    __syncthreads();

    int m = tid & 63, jb = (tid >> 6) * 16;
    u64 m1[8];
#pragma unroll
    for (int p = 0; p < 8; p++) m1[p] = pack2(mlp_b1[jb + 2 * p], mlp_b1[jb + 2 * p + 1]);
    const __half* hrow = (const __half*)(sm + SML_A0 + m * ASTR);
#pragma unroll 4
    for (int k = 0; k < 128; k++) {
        u64 hd = dup2(__half2float(hrow[k]));
        const u64* wp = (const u64*)&sW1[k * 128 + jb];
#pragma unroll
        for (int p = 0; p < 8; p++) m1[p] = ffma2(wp[p], hd, m1[p]);
    }
    float v = 0.0f;
#pragma unroll
    for (int p = 0; p < 8; p++) {
        float2 a = up2(m1[p]);
        v += fmaxf(a.x, 0.0f) * mlp_W2[jb + 2 * p]
           + fmaxf(a.y, 0.0f) * mlp_W2[jb + 2 * p + 1];
    }
    float* part = (float*)(sm + SML_PART);
    part[m * 8 + (tid >> 6)] = v;
    __syncthreads();
    if (tid < 64) {
        float s = mlp_b2[0];
#pragma unroll
        for (int p = 0; p < 8; p++) s += part[tid * 8 + p];
        scores_out[n0 + tid] = s;
    }
}

// ---------------- K7: logsumexp + BCE ----------------
__global__ void k_final(const float* __restrict__ label, float* __restrict__ out) {
    __shared__ float red[Bsz];
    int b = threadIdx.x;
    const float* sc = out + 1 + Bsz + b * Pn;
    float mx = -1e30f;
#pragma unroll
    for (int p = 0; p < Pn; p++) mx = fmaxf(mx, sc[p] * 0.5f);
    float s = 0.0f;
#pragma unroll
    for (int p = 0; p < Pn; p++) s += expf(sc[p] * 0.5f - mx);
    float lse = mx + logf(s);
    float pr = 1.0f / (1.0f + expf(-lse));
    out[1 + b] = pr;
    float pc = fminf(fmaxf(pr, 1e-7f), 1.0f - 1e-7f);
    float lb = label[b];
    red[b] = -(lb * logf(pc) + (1.0f - lb) * logf(1.0f - pc));
    __syncthreads();
    for (int st = Bsz / 2; st > 0; st >>= 1) {
        if (b < st) red[b] += red[b + st];
        __syncthreads();
    }
    if (b == 0) out[0] = red[0] / (float)Bsz;
}

// ---------------- launch ----------------
extern "C" void kernel_launch(void* const* d_in, const int* in_sizes, int n_in,
                              void* d_out, int out_size) {
    const int*   item1     = (const int*)d_in[0];
    const int*   item2     = (const int*)d_in[1];
    const int*   paths     = (const int*)d_in[2];
    const int*   edges     = (const int*)d_in[3];
    const float* label     = (const float*)d_in[4];
    const float* doc_table = (const float*)d_in[5];
    const float* ent_table = (const float*)d_in[6];
    const float* rel_table = (const float*)d_in[7];
    const float* nc_W1 = (const float*)d_in[8];
    const float* nc_b1 = (const float*)d_in[9];
    const float* nc_W2 = (const float*)d_in[10];
    const float* nc_b2 = (const float*)d_in[11];
    const float* ec_W  = (const float*)d_in[12];
    const float* ec_b  = (const float*)d_in[13];
    const float* rc_W  = (const float*)d_in[14];
    const float* rc_b  = (const float*)d_in[15];
    const float* W_ih  = (const float*)d_in[16];
    const float* W_hh  = (const float*)d_in[17];
    const float* b_ih  = (const float*)d_in[18];
    const float* b_hh  = (const float*)d_in[19];
    const float* mlp_W1 = (const float*)d_in[20];
    const float* mlp_b1 = (const float*)d_in[21];
    const float* mlp_W2 = (const float*)d_in[22];
    const float* mlp_b2 = (const float*)d_in[23];
    float* out = (float*)d_out;

    cudaFuncSetAttribute(k_gemm_mma, cudaFuncAttributeMaxDynamicSharedMemorySize, SMG_TOTAL);
    cudaFuncSetAttribute(k_lstm_mma, cudaFuncAttributeMaxDynamicSharedMemorySize, SML_TOTAL);

    k_transpose<<<(512 * 128 + 511) / 512, 512>>>(W_ih, W_hh);
    k_news<<<2 * Bsz / 8, 128>>>(item1, item2, doc_table, nc_W1, nc_b1, nc_W2, nc_b2);
    k_rel<<<NREL, 512>>>(rel_table, rc_W, rc_b, b_ih, b_hh);
    k_node<<<NPL / 16, 128>>>(paths, ent_table, ec_W, ec_b);
    k_gemm_mma<<<dim3(MTOT / 128, 2), 512, SMG_TOTAL>>>();
    k_lstm_mma<<<Nseq / 64, 512, SML_TOTAL>>>(edges, mlp_W1, mlp_b1, mlp_W2, mlp_b2,
                                              out + 1 + Bsz);
    k_final<<<1, Bsz>>>(label, out);
}

// round 6
// speedup vs baseline: 2.8771x; 1.0663x over previous
#include <cuda_runtime.h>
#include <cuda_fp16.h>
#include <math.h>
#include <stdint.h>

typedef unsigned long long u64;

#define Bsz   1024
#define Pn    20
#define Ln    3
#define Tn    5
#define En    128
#define Nseq  (Bsz*Pn)          /* 20480 */
#define NPL   (Bsz*Pn*Ln)       /* 61440 */
#define NREL  60
#define DDOC  768
#define DENT  100
#define KPAD  112               /* DENT padded to 7*16 */
#define MTOT  (NPL + 2*Bsz)     /* 63488 = 496*128 */

// ---------------- device scratch ----------------
__device__ __half g_AE [(size_t)MTOT * 128];    // f16 A rows (nodes, then news1, news2)
__device__ __half g_Bn [512 * 128];             // f16 W_ih[:,0:128] quad-packed rows c=j*4+g
__device__ __half g_Bh [512 * 128];             // f16 W_hh quad-packed
__device__ __half g_Wec[128 * KPAD];            // f16 ec_W^T [c][k], zero-padded k>=100
__device__ float  g_WTrel[128 * 512];           // f32 [k][c]
__device__ float  g_relGb[NREL * 512];          // relC@WTrel + bias, PERMUTED quads, f32
__device__ __half g_G16 [(size_t)MTOT * 512];   // input-gate preacts, PERMUTED quads, f16

// ---- fast transcendentals (MUFU.TANH, sm_75+) ----
__device__ __forceinline__ float tanha(float x) {
    float y; asm("tanh.approx.f32 %0, %1;" : "=f"(y) : "f"(x)); return y;
}
__device__ __forceinline__ float siga(float x) {
    return fmaf(tanha(x * 0.5f), 0.5f, 0.5f);
}

// ---- f32x2 helpers ----
__device__ __forceinline__ u64 ffma2(u64 a, u64 b, u64 c) {
    u64 d; asm("fma.rn.f32x2 %0, %1, %2, %3;" : "=l"(d) : "l"(a), "l"(b), "l"(c)); return d;
}
__device__ __forceinline__ u64 dup2(float x) {
    u64 d; unsigned xi = __float_as_uint(x);
    asm("mov.b64 %0, {%1, %1};" : "=l"(d) : "r"(xi)); return d;
}
__device__ __forceinline__ u64 pack2(float lo, float hi) {
    u64 d; asm("mov.b64 %0, {%1, %2};" : "=l"(d) : "r"(__float_as_uint(lo)), "r"(__float_as_uint(hi)));
    return d;
}
__device__ __forceinline__ float2 up2(u64 v) {
    unsigned lo, hi; asm("mov.b64 {%0, %1}, %2;" : "=r"(lo), "=r"(hi) : "l"(v));
    return make_float2(__uint_as_float(lo), __uint_as_float(hi));
}

// ---- mma / ldmatrix (family-safe PTX) ----
__device__ __forceinline__ uint32_t s2u(const void* p) {
    uint32_t a;
    asm("{ .reg .u64 t; cvta.to.shared.u64 t, %1; cvt.u32.u64 %0, t; }" : "=r"(a) : "l"(p));
    return a;
}
__device__ __forceinline__ void ldmA(uint32_t* r, uint32_t addr) {
    asm volatile("ldmatrix.sync.aligned.m8n8.x4.shared.b16 {%0,%1,%2,%3}, [%4];"
                 : "=r"(r[0]), "=r"(r[1]), "=r"(r[2]), "=r"(r[3]) : "r"(addr));
}
__device__ __forceinline__ void ldmB(uint32_t* r, uint32_t addr) {
    asm volatile("ldmatrix.sync.aligned.m8n8.x2.shared.b16 {%0,%1}, [%2];"
                 : "=r"(r[0]), "=r"(r[1]) : "r"(addr));
}
__device__ __forceinline__ void mma16816(float* d, const uint32_t* a, const uint32_t* b) {
    asm volatile("mma.sync.aligned.m16n8k16.row.col.f32.f16.f16.f32 "
        "{%0,%1,%2,%3}, {%4,%5,%6,%7}, {%8,%9}, {%0,%1,%2,%3};"
        : "+f"(d[0]), "+f"(d[1]), "+f"(d[2]), "+f"(d[3])
        : "r"(a[0]), "r"(a[1]), "r"(a[2]), "r"(a[3]), "r"(b[0]), "r"(b[1]));
}

#define ASTR  272   /* 256B-row operand stride */
#define CSTR  528   /* C staging stride (512B rows) */
#define CKSTR 240   /* 224B-row operand stride (K=112): 8-row ldm banks all distinct */

// ---------------- K0: transpose + pack weights ----------------
__global__ void k_transpose(const float* __restrict__ W_ih, const float* __restrict__ W_hh,
                            const float* __restrict__ ec_W) {
    int idx = blockIdx.x * blockDim.x + threadIdx.x;
    if (idx < 128 * KPAD) {
        int c = idx / KPAD, k = idx - c * KPAD;
        g_Wec[idx] = (k < DENT) ? __float2half_rn(ec_W[k * 128 + c]) : __half(0.0f);
    }
    if (idx >= 512 * 128) return;
    int c = idx >> 7, k = idx & 127;
    int row = (c & 3) * 128 + (c >> 2);
    g_Bn[c * 128 + k] = __float2half_rn(W_ih[row * 256 + k]);
    g_Bh[c * 128 + k] = __float2half_rn(W_hh[row * 128 + k]);
    g_WTrel[k * 512 + c] = W_ih[row * 256 + 128 + k];
}

// ---------------- K1: news compress -> f16 rows ----------------
__global__ void k_news(const int* __restrict__ item1, const int* __restrict__ item2,
                       const float* __restrict__ doc_table,
                       const float* __restrict__ W1, const float* __restrict__ b1,
                       const float* __restrict__ W2, const float* __restrict__ b2) {
    __shared__ float ds[8 * DDOC];
    __shared__ float h1[8 * En];
    __shared__ int   items[8];
    int r0 = blockIdx.x * 8;
    int tid = threadIdx.x;
    if (tid < 8) {
        int row = r0 + tid;
        items[tid] = (row < Bsz) ? item1[row] : item2[row - Bsz];
    }
    __syncthreads();
    for (int idx = tid; idx < 8 * DDOC; idx += 128) {
        int r = idx / DDOC, k = idx % DDOC;
        ds[idx] = doc_table[(size_t)items[r] * DDOC + k];
    }
    __syncthreads();
    float a[8];
    float bb = b1[tid];
#pragma unroll
    for (int r = 0; r < 8; r++) a[r] = bb;
    for (int k = 0; k < DDOC; k++) {
        float w = W1[k * En + tid];
#pragma unroll
        for (int r = 0; r < 8; r++) a[r] += ds[r * DDOC + k] * w;
    }
#pragma unroll
    for (int r = 0; r < 8; r++) {
        float v = a[r];
        h1[r * En + tid] = (v > 0.0f) ? v : expm1f(v);
    }
    __syncthreads();
    float bb2 = b2[tid];
#pragma unroll
    for (int r = 0; r < 8; r++) a[r] = bb2;
    for (int k = 0; k < En; k++) {
        float w = W2[k * En + tid];
#pragma unroll
        for (int r = 0; r < 8; r++) a[r] += h1[r * En + k] * w;
    }
#pragma unroll
    for (int r = 0; r < 8; r++)
        g_AE[(size_t)(NPL + r0 + r) * En + tid] = __float2half_rn(tanhf(a[r]));
}

// ---------------- K2: relation compress + gate projection (merged, permuted out) ----------------
__global__ void k_rel(const float* __restrict__ rel_table,
                      const float* __restrict__ W, const float* __restrict__ b,
                      const float* __restrict__ b_ih, const float* __restrict__ b_hh) {
    __shared__ float rr[DENT];
    __shared__ float rc[En];
    int row = blockIdx.x, tid = threadIdx.x;
    if (tid < DENT) rr[tid] = rel_table[row * DENT + tid];
    __syncthreads();
    if (tid < En) {
        float s = b[tid];
        for (int k = 0; k < DENT; k++) s += rr[k] * W[k * En + tid];
        rc[tid] = tanhf(s);
    }
    __syncthreads();
    int c = tid;
    int j = c >> 2, g = c & 3;
    int gidx = g * 128 + j;
    float s = b_ih[gidx] + b_hh[gidx];
    for (int k = 0; k < En; k++) s += rc[k] * g_WTrel[k * 512 + c];
    int q = c >> 2;
    int p = (q & ~31) | ((q & 1) << 4) | ((q & 31) >> 1);
    g_relGb[row * 512 + p * 4 + g] = s;
}

// ---------------- K3: entity gather + HMMA compress -> f16 rows of g_AE ----------------
#define SMC_A 0                            /* 128 * CKSTR = 30720 */
#define SMC_B (128 * CKSTR)                /* 30720 .. 61440 */
#define SMC_C (2 * 128 * CKSTR)            /* C staging 128 x 272 = 34816 */
#define SMC_TOTAL (SMC_C + 128 * ASTR)     /* 96256 */
__global__ __launch_bounds__(512, 1) void k_compress_mma(const int* __restrict__ paths,
                                                         const float* __restrict__ ent_table,
                                                         const float* __restrict__ ec_b) {
    extern __shared__ char sm[];
    __shared__ int spath[128];
    int tid = threadIdx.x, w = tid >> 5, l = tid & 31;
    int wm = w & 3, wn = w >> 2;
    int row0 = blockIdx.x * 128;

    if (tid < 128) spath[tid] = paths[row0 + tid];
    __syncthreads();
    // stage A: gathered entity rows, f16, K padded to 112
    for (int idx = tid; idx < 128 * KPAD; idx += 512) {
        int r = idx / KPAD, k = idx - r * KPAD;
        float v = (k < DENT) ? ent_table[(size_t)spath[r] * DENT + k] : 0.0f;
        *(__half*)(sm + SMC_A + r * CKSTR + k * 2) = __float2half_rn(v);
    }
    // stage B: ec_W^T f16
    for (int idx = tid; idx < 128 * KPAD; idx += 512) {
        int r = idx / KPAD, k = idx - r * KPAD;
        *(__half*)(sm + SMC_B + r * CKSTR + k * 2) = g_Wec[idx];
    }
    __syncthreads();

    uint32_t base = s2u(sm);
    int g8 = l & 7;
    uint32_t aBase = base + SMC_A + (uint32_t)(wm * 32 + g8 + ((l >> 3) & 1) * 8) * CKSTR
                   + ((l >> 4) & 1) * 16;
    uint32_t bBase = base + SMC_B + (uint32_t)(wn * 32 + g8) * CKSTR + ((l >> 3) & 1) * 16;

    float acc[2][4][4];
#pragma unroll
    for (int mt = 0; mt < 2; mt++)
#pragma unroll
        for (int nt = 0; nt < 4; nt++)
#pragma unroll
            for (int q = 0; q < 4; q++) acc[mt][nt][q] = 0.0f;

#pragma unroll
    for (int kt = 0; kt < 7; kt++) {
        uint32_t a[2][4];
        ldmA(a[0], aBase + kt * 32);
        ldmA(a[1], aBase + 16 * CKSTR + kt * 32);
#pragma unroll
        for (int nt = 0; nt < 4; nt++) {
            uint32_t b[2];
            ldmB(b, bBase + nt * 8 * CKSTR + kt * 32);
            mma16816(acc[0][nt], a[0], b);
            mma16816(acc[1][nt], a[1], b);
        }
    }
    __syncthreads();

    // epilogue: tanh(acc + ec_b[col]) -> f16 staged, then coalesced stream
    int tg = l & 3, gg = l >> 2;
#pragma unroll
    for (int mt = 0; mt < 2; mt++) {
        int r = wm * 32 + mt * 16 + gg;
#pragma unroll
        for (int nt = 0; nt < 4; nt++) {
            int cc = wn * 32 + nt * 8 + 2 * tg;
            float b0 = __ldg(ec_b + cc), b1 = __ldg(ec_b + cc + 1);
            *(__half2*)(sm + SMC_C + r * ASTR + cc * 2) =
                __floats2half2_rn(tanha(acc[mt][nt][0] + b0), tanha(acc[mt][nt][1] + b1));
            *(__half2*)(sm + SMC_C + (r + 8) * ASTR + cc * 2) =
                __floats2half2_rn(tanha(acc[mt][nt][2] + b0), tanha(acc[mt][nt][3] + b1));
        }
    }
    __syncthreads();
    for (int it = tid; it < 128 * 16; it += 512) {
        int r = it >> 4, bb = it & 15;
        uint4 v = *(uint4*)(sm + SMC_C + r * ASTR + bb * 16);
        *(uint4*)((char*)g_AE + (size_t)(row0 + r) * 256 + bb * 16) = v;
    }
}

// ---------------- K4: HMMA GEMM  g_G16 = g_AE @ g_Bn^T (permuted fp16 out) ----------------
#define SMG_A 0
#define SMG_B (128 * ASTR)                /* 34816 */
#define SMG_TOTAL (SMG_B + 256 * ASTR)    /* 104448 */
__global__ __launch_bounds__(512, 1) void k_gemm_mma() {
    extern __shared__ char sm[];
    int tid = threadIdx.x, w = tid >> 5, l = tid & 31;
    int wm = w & 3, wn = w >> 2;
    int row0 = blockIdx.x * 128;
    int n0b  = blockIdx.y * 256;

    const uint4* Ag = (const uint4*)g_AE;
    for (int idx = tid; idx < 128 * 16; idx += 512) {
        int r = idx >> 4, c4 = idx & 15;
        *(uint4*)(sm + SMG_A + r * ASTR + c4 * 16) = Ag[(size_t)(row0 + r) * 16 + c4];
    }
    const uint4* Bg = (const uint4*)g_Bn;
    for (int idx = tid; idx < 256 * 16; idx += 512) {
        int n = idx >> 4, c4 = idx & 15;
        *(uint4*)(sm + SMG_B + n * ASTR + c4 * 16) = Bg[(size_t)(n0b + n) * 16 + c4];
    }
    __syncthreads();

    uint32_t base = s2u(sm);
    int g8 = l & 7;
    uint32_t aBase = base + SMG_A + (uint32_t)(wm * 32 + g8 + ((l >> 3) & 1) * 8) * ASTR
                   + ((l >> 4) & 1) * 16;
    uint32_t bBase = base + SMG_B + (uint32_t)(wn * 64 + g8) * ASTR + ((l >> 3) & 1) * 16;

    float acc[2][8][4];
#pragma unroll
    for (int mt = 0; mt < 2; mt++)
#pragma unroll
        for (int nt = 0; nt < 8; nt++)
#pragma unroll
            for (int q = 0; q < 4; q++) acc[mt][nt][q] = 0.0f;

#pragma unroll
    for (int kt = 0; kt < 8; kt++) {
        uint32_t a[2][4];
        ldmA(a[0], aBase + kt * 32);
        ldmA(a[1], aBase + 16 * ASTR + kt * 32);
#pragma unroll
        for (int nt = 0; nt < 8; nt++) {
            uint32_t b[2];
            ldmB(b, bBase + nt * 8 * ASTR + kt * 32);
            mma16816(acc[0][nt], a[0], b);
            mma16816(acc[1][nt], a[1], b);
        }
    }
    __syncthreads();

    int tg = l & 3, gg = l >> 2;
#pragma unroll
    for (int mt = 0; mt < 2; mt++) {
        int r = wm * 32 + mt * 16 + gg;
#pragma unroll
        for (int nt = 0; nt < 8; nt++) {
            int qg = wn * 16 + nt * 2 + (tg >> 1);
            int pl = (qg & ~31) | ((qg & 1) << 4) | ((qg & 31) >> 1);
            *(__half2*)(sm + r * CSTR + pl * 8 + (tg & 1) * 4) =
                __floats2half2_rn(acc[mt][nt][0], acc[mt][nt][1]);
            *(__half2*)(sm + (r + 8) * CSTR + pl * 8 + (tg & 1) * 4) =
                __floats2half2_rn(acc[mt][nt][2], acc[mt][nt][3]);
        }
    }
    __syncthreads();
    for (int it = tid; it < 128 * 32; it += 512) {
        int r = it >> 5, bb = it & 31;
        uint4 v = *(uint4*)(sm + r * CSTR + bb * 16);
        *(uint4*)((char*)g_G16 + (size_t)(row0 + r) * 1024 + (size_t)n0b * 2 + bb * 16) = v;
    }
}

// ---------------- K5: HMMA LSTM + fused MLP ----------------
#define SML_A0 0
#define SML_A1 (64 * ASTR)
#define SML_B  (2 * 64 * ASTR)
#define SML_W1 SML_B
#define SML_PART (SML_B + 512 * ASTR)
#define SML_TOTAL (SML_PART + 2048)
__global__ __launch_bounds__(512, 1) void k_lstm_mma(const int* __restrict__ edges,
                                                     const float* __restrict__ mlp_W1,
                                                     const float* __restrict__ mlp_b1,
                                                     const float* __restrict__ mlp_W2,
                                                     const float* __restrict__ mlp_b2,
                                                     float* __restrict__ scores_out) {
    extern __shared__ char sm[];
    int tid = threadIdx.x, w = tid >> 5, l = tid & 31;
    int wm = w & 3, wn = w >> 2;
    int n0 = blockIdx.x * 64;
    int g8 = l & 7, tg = l & 3, gg = l >> 2;
    int odd = tg & 1;
    int par = tg >> 1;

    const uint4* Bg = (const uint4*)g_Bh;
    for (int idx = tid; idx < 512 * 16; idx += 512) {
        int n = idx >> 4, c4 = idx & 15;
        *(uint4*)(sm + SML_B + n * ASTR + c4 * 16) = Bg[(size_t)n * 16 + c4];
    }
    __syncthreads();

    uint32_t base = s2u(sm);
    uint32_t aLane = (uint32_t)(wm * 16 + g8 + ((l >> 3) & 1) * 8) * ASTR + ((l >> 4) & 1) * 16;
    uint32_t bBase = base + SML_B + (uint32_t)(wn * 128 + g8) * ASTR + ((l >> 3) & 1) * 16;

    int r_loc = wm * 16 + gg + odd * 8;
    int seq = n0 + r_loc;
    int bIdx = seq / Pn;

    float cst[16];
#pragma unroll
    for (int q = 0; q < 16; q++) cst[q] = 0.0f;

    for (int t = 0; t < Tn; t++) {
        uint32_t aRd = base + ((t & 1) ? SML_A0 : SML_A1) + aLane;
        char* hWr = sm + ((t & 1) ? SML_A1 : SML_A0);
        int rowG = (t == 0) ? NPL + bIdx
                 : (t == 4) ? NPL + Bsz + bIdx
                 : seq * Ln + (t - 1);
        int e = (t < Ln) ? edges[seq * Ln + t] : 0;
        const uint4* gp = (const uint4*)((const char*)g_G16 + (size_t)rowG * 1024
                                         + (size_t)(wn * 32 + par * 16) * 8);
        const float4* rp = (const float4*)(g_relGb + (size_t)e * 512
                                           + (wn * 32 + par * 16) * 4);

#pragma unroll
        for (int half = 0; half < 2; half++) {
            uint4 gu[4];
#pragma unroll
            for (int k2 = 0; k2 < 4; k2++) gu[k2] = gp[half * 4 + k2];

            float acc[8][4];
#pragma unroll
            for (int nt = 0; nt < 8; nt++)
#pragma unroll
                for (int q = 0; q < 4; q++) acc[nt][q] = 0.0f;
            if (t > 0) {
#pragma unroll
                for (int kt = 0; kt < 8; kt++) {
                    uint32_t a[4];
                    ldmA(a, aRd + kt * 32);
#pragma unroll
                    for (int ntl = 0; ntl < 8; ntl++) {
                        uint32_t b[2];
                        ldmB(b, bBase + (half * 8 + ntl) * 8 * ASTR + kt * 32);
                        mma16816(acc[ntl], a, b);
                    }
                }
            }
#pragma unroll
            for (int ntl = 0; ntl < 8; ntl++) {
                int nt = half * 8 + ntl;
                float d0 = acc[ntl][0], d1 = acc[ntl][1];
                float d2 = acc[ntl][2], d3 = acc[ntl][3];
                float x0 = __shfl_xor_sync(0xffffffffu, d0, 1);
                float x1 = __shfl_xor_sync(0xffffffffu, d1, 1);
                float x2 = __shfl_xor_sync(0xffffffffu, d2, 1);
                float x3 = __shfl_xor_sync(0xffffffffu, d3, 1);
                float gi = odd ? x2 : d0;
                float gf = odd ? x3 : d1;
                float gG = odd ? d2 : x0;
                float gO = odd ? d3 : x1;
                __half2 hif = ((const __half2*)&gu[ntl >> 1])[(ntl & 1) * 2 + 0];
                __half2 hgo = ((const __half2*)&gu[ntl >> 1])[(ntl & 1) * 2 + 1];
                float2 fif = __half22float2(hif);
                float2 fgo = __half22float2(hgo);
                float4 r4 = rp[nt];
                gi += fif.x + r4.x;
                gf += fif.y + r4.y;
                gG += fgo.x + r4.z;
                gO += fgo.y + r4.w;
                cst[nt] = siga(gf) * cst[nt] + siga(gi) * tanha(gG);
                float hv = siga(gO) * tanha(cst[nt]);
                int q = wn * 32 + nt * 2 + par;
                *(__half*)(hWr + r_loc * ASTR + q * 2) = __float2half_rn(hv);
            }
        }
        __syncthreads();
    }

    // ---- fused MLP: final h in buffer A0 ----
    float* sW1 = (float*)(sm + SML_W1);
    for (int idx = tid; idx < 128 * 128; idx += 512) sW1[idx] = mlp_W1[idx];
    __syncthreads();

    int m = tid & 63, jb = (tid >> 6) * 16;
    u64 m1[8];
#pragma unroll
    for (int p = 0; p < 8; p++) m1[p] = pack2(mlp_b1[jb + 2 * p], mlp_b1[jb + 2 * p + 1]);
    const __half* hrow = (const __half*)(sm + SML_A0 + m * ASTR);
#pragma unroll 4
    for (int k = 0; k < 128; k++) {
        u64 hd = dup2(__half2float(hrow[k]));
        const u64* wp = (const u64*)&sW1[k * 128 + jb];
#pragma unroll
        for (int p = 0; p < 8; p++) m1[p] = ffma2(wp[p], hd, m1[p]);
    }
    float v = 0.0f;
#pragma unroll
    for (int p = 0; p < 8; p++) {
        float2 a = up2(m1[p]);
        v += fmaxf(a.x, 0.0f) * mlp_W2[jb + 2 * p]
           + fmaxf(a.y, 0.0f) * mlp_W2[jb + 2 * p + 1];
    }
    float* part = (float*)(sm + SML_PART);
    part[m * 8 + (tid >> 6)] = v;
    __syncthreads();
    if (tid < 64) {
        float s = mlp_b2[0];
#pragma unroll
        for (int p = 0; p < 8; p++) s += part[tid * 8 + p];
        scores_out[n0 + tid] = s;
    }
}

// ---------------- K7: logsumexp + BCE ----------------
__global__ void k_final(const float* __restrict__ label, float* __restrict__ out) {
    __shared__ float red[Bsz];
    int b = threadIdx.x;
    const float* sc = out + 1 + Bsz + b * Pn;
    float mx = -1e30f;
#pragma unroll
    for (int p = 0; p < Pn; p++) mx = fmaxf(mx, sc[p] * 0.5f);
    float s = 0.0f;
#pragma unroll
    for (int p = 0; p < Pn; p++) s += expf(sc[p] * 0.5f - mx);
    float lse = mx + logf(s);
    float pr = 1.0f / (1.0f + expf(-lse));
    out[1 + b] = pr;
    float pc = fminf(fmaxf(pr, 1e-7f), 1.0f - 1e-7f);
    float lb = label[b];
    red[b] = -(lb * logf(pc) + (1.0f - lb) * logf(1.0f - pc));
    __syncthreads();
    for (int st = Bsz / 2; st > 0; st >>= 1) {
        if (b < st) red[b] += red[b + st];
        __syncthreads();
    }
    if (b == 0) out[0] = red[0] / (float)Bsz;
}

// ---------------- launch ----------------
extern "C" void kernel_launch(void* const* d_in, const int* in_sizes, int n_in,
                              void* d_out, int out_size) {
    const int*   item1     = (const int*)d_in[0];
    const int*   item2     = (const int*)d_in[1];
    const int*   paths     = (const int*)d_in[2];
    const int*   edges     = (const int*)d_in[3];
    const float* label     = (const float*)d_in[4];
    const float* doc_table = (const float*)d_in[5];
    const float* ent_table = (const float*)d_in[6];
    const float* rel_table = (const float*)d_in[7];
    const float* nc_W1 = (const float*)d_in[8];
    const float* nc_b1 = (const float*)d_in[9];
    const float* nc_W2 = (const float*)d_in[10];
    const float* nc_b2 = (const float*)d_in[11];
    const float* ec_W  = (const float*)d_in[12];
    const float* ec_b  = (const float*)d_in[13];
    const float* rc_W  = (const float*)d_in[14];
    const float* rc_b  = (const float*)d_in[15];
    const float* W_ih  = (const float*)d_in[16];
    const float* W_hh  = (const float*)d_in[17];
    const float* b_ih  = (const float*)d_in[18];
    const float* b_hh  = (const float*)d_in[19];
    const float* mlp_W1 = (const float*)d_in[20];
    const float* mlp_b1 = (const float*)d_in[21];
    const float* mlp_W2 = (const float*)d_in[22];
    const float* mlp_b2 = (const float*)d_in[23];
    float* out = (float*)d_out;

    cudaFuncSetAttribute(k_compress_mma, cudaFuncAttributeMaxDynamicSharedMemorySize, SMC_TOTAL);
    cudaFuncSetAttribute(k_gemm_mma, cudaFuncAttributeMaxDynamicSharedMemorySize, SMG_TOTAL);
    cudaFuncSetAttribute(k_lstm_mma, cudaFuncAttributeMaxDynamicSharedMemorySize, SML_TOTAL);

    k_transpose<<<(512 * 128 + 511) / 512, 512>>>(W_ih, W_hh, ec_W);
    k_news<<<2 * Bsz / 8, 128>>>(item1, item2, doc_table, nc_W1, nc_b1, nc_W2, nc_b2);
    k_rel<<<NREL, 512>>>(rel_table, rc_W, rc_b, b_ih, b_hh);
    k_compress_mma<<<NPL / 128, 512, SMC_TOTAL>>>(paths, ent_table, ec_b);
    k_gemm_mma<<<dim3(MTOT / 128, 2), 512, SMG_TOTAL>>>();
    k_lstm_mma<<<Nseq / 64, 512, SML_TOTAL>>>(edges, mlp_W1, mlp_b1, mlp_W2, mlp_b2,
                                              out + 1 + Bsz);
    k_final<<<1, Bsz>>>(label, out);
}

// round 7
// speedup vs baseline: 3.2769x; 1.1389x over previous
#include <cuda_runtime.h>
#include <cuda_fp16.h>
#include <math.h>
#include <stdint.h>

typedef unsigned long long u64;

#define Bsz   1024
#define Pn    20
#define Ln    3
#define Tn    5
#define En    128
#define Nseq  (Bsz*Pn)          /* 20480 */
#define NPL   (Bsz*Pn*Ln)       /* 61440 */
#define NREL  60
#define DDOC  768
#define DENT  100
#define KPAD  112               /* DENT padded to 7*16 */
#define MTOT  (NPL + 2*Bsz)     /* 63488 = 496*128 */

// ---------------- device scratch ----------------
__device__ __half g_AE [(size_t)MTOT * 128];    // f16 A rows (nodes, then news1, news2)
__device__ __half g_Bn [512 * 128];             // f16 W_ih[:,0:128] quad-packed rows c=j*4+g
__device__ __half g_Bh [512 * 128];             // f16 W_hh quad-packed
__device__ __half g_Wec[128 * KPAD];            // f16 ec_W^T [c][k], zero-padded k>=100
__device__ float  g_WTrel[128 * 512];           // f32 [k][c]
__device__ float  g_relGb[NREL * 512];          // relC@WTrel + bias, PERMUTED quads, f32
__device__ __half g_G16 [(size_t)MTOT * 512];   // input-gate preacts, PERMUTED quads, f16

// ---- fast transcendentals (MUFU.TANH, sm_75+) ----
__device__ __forceinline__ float tanha(float x) {
    float y; asm("tanh.approx.f32 %0, %1;" : "=f"(y) : "f"(x)); return y;
}
__device__ __forceinline__ float siga(float x) {
    return fmaf(tanha(x * 0.5f), 0.5f, 0.5f);
}

// ---- f32x2 helpers ----
__device__ __forceinline__ u64 ffma2(u64 a, u64 b, u64 c) {
    u64 d; asm("fma.rn.f32x2 %0, %1, %2, %3;" : "=l"(d) : "l"(a), "l"(b), "l"(c)); return d;
}
__device__ __forceinline__ u64 dup2(float x) {
    u64 d; unsigned xi = __float_as_uint(x);
    asm("mov.b64 %0, {%1, %1};" : "=l"(d) : "r"(xi)); return d;
}
__device__ __forceinline__ u64 pack2(float lo, float hi) {
    u64 d; asm("mov.b64 %0, {%1, %2};" : "=l"(d) : "r"(__float_as_uint(lo)), "r"(__float_as_uint(hi)));
    return d;
}
__device__ __forceinline__ float2 up2(u64 v) {
    unsigned lo, hi; asm("mov.b64 {%0, %1}, %2;" : "=r"(lo), "=r"(hi) : "l"(v));
    return make_float2(__uint_as_float(lo), __uint_as_float(hi));
}

// ---- mma / ldmatrix (family-safe PTX) ----
__device__ __forceinline__ uint32_t s2u(const void* p) {
    uint32_t a;
    asm("{ .reg .u64 t; cvta.to.shared.u64 t, %1; cvt.u32.u64 %0, t; }" : "=r"(a) : "l"(p));
    return a;
}
__device__ __forceinline__ void ldmA(uint32_t* r, uint32_t addr) {
    asm volatile("ldmatrix.sync.aligned.m8n8.x4.shared.b16 {%0,%1,%2,%3}, [%4];"
                 : "=r"(r[0]), "=r"(r[1]), "=r"(r[2]), "=r"(r[3]) : "r"(addr));
}
__device__ __forceinline__ void ldmB(uint32_t* r, uint32_t addr) {
    asm volatile("ldmatrix.sync.aligned.m8n8.x2.shared.b16 {%0,%1}, [%2];"
                 : "=r"(r[0]), "=r"(r[1]) : "r"(addr));
}
__device__ __forceinline__ void mma16816(float* d, const uint32_t* a, const uint32_t* b) {
    asm volatile("mma.sync.aligned.m16n8k16.row.col.f32.f16.f16.f32 "
        "{%0,%1,%2,%3}, {%4,%5,%6,%7}, {%8,%9}, {%0,%1,%2,%3};"
        : "+f"(d[0]), "+f"(d[1]), "+f"(d[2]), "+f"(d[3])
        : "r"(a[0]), "r"(a[1]), "r"(a[2]), "r"(a[3]), "r"(b[0]), "r"(b[1]));
}

#define ASTR  272   /* 256B-row operand stride */
#define CSTR  528   /* C staging stride (512B rows) */
#define CKSTR 240   /* 224B-row operand stride (K=112) */
#define DSTR  10    /* k_news pair-row stride (words) */

// ---------------- K0: transpose + pack weights ----------------
__global__ void k_transpose(const float* __restrict__ W_ih, const float* __restrict__ W_hh,
                            const float* __restrict__ ec_W) {
    int idx = blockIdx.x * blockDim.x + threadIdx.x;
    if (idx < 128 * KPAD) {
        int c = idx / KPAD, k = idx - c * KPAD;
        g_Wec[idx] = (k < DENT) ? __float2half_rn(ec_W[k * 128 + c]) : __half(0.0f);
    }
    if (idx >= 512 * 128) return;
    int c = idx >> 7, k = idx & 127;
    int row = (c & 3) * 128 + (c >> 2);
    g_Bn[c * 128 + k] = __float2half_rn(W_ih[row * 256 + k]);
    g_Bh[c * 128 + k] = __float2half_rn(W_hh[row * 128 + k]);
    g_WTrel[k * 512 + c] = W_ih[row * 256 + 128 + k];
}

// ---------------- K1: news compress -> f16 rows (f32x2 both phases) ----------------
__global__ void k_news(const int* __restrict__ item1, const int* __restrict__ item2,
                       const float* __restrict__ doc_table,
                       const float* __restrict__ W1, const float* __restrict__ b1,
                       const float* __restrict__ W2, const float* __restrict__ b2) {
    __shared__ __align__(16) float dsp[DDOC * DSTR];   // [k][r], stride 10
    __shared__ __align__(16) float h1p[En * DSTR];
    __shared__ int items[8];
    int r0 = blockIdx.x * 8;
    int tid = threadIdx.x;
    if (tid < 8) {
        int row = r0 + tid;
        items[tid] = (row < Bsz) ? item1[row] : item2[row - Bsz];
    }
    __syncthreads();
    // stage doc rows transposed into pair layout
    for (int k = tid; k < DDOC; k += 128) {
#pragma unroll
        for (int r = 0; r < 8; r++)
            dsp[k * DSTR + r] = doc_table[(size_t)items[r] * DDOC + k];
    }
    __syncthreads();
    // phase 1: elu(doc @ W1 + b1)
    u64 acc2[4];
    u64 bd = dup2(b1[tid]);
#pragma unroll
    for (int p = 0; p < 4; p++) acc2[p] = bd;
    for (int k = 0; k < DDOC; k++) {
        u64 wd = dup2(W1[k * En + tid]);
        const u64* hp = (const u64*)&dsp[k * DSTR];
#pragma unroll
        for (int p = 0; p < 4; p++) acc2[p] = ffma2(hp[p], wd, acc2[p]);
    }
#pragma unroll
    for (int p = 0; p < 4; p++) {
        float2 a = up2(acc2[p]);
        h1p[tid * DSTR + 2 * p]     = (a.x > 0.0f) ? a.x : expm1f(a.x);
        h1p[tid * DSTR + 2 * p + 1] = (a.y > 0.0f) ? a.y : expm1f(a.y);
    }
    __syncthreads();
    // phase 2: tanh(h1 @ W2 + b2) -> f16
    u64 bd2 = dup2(b2[tid]);
#pragma unroll
    for (int p = 0; p < 4; p++) acc2[p] = bd2;
    for (int k = 0; k < En; k++) {
        u64 wd = dup2(W2[k * En + tid]);
        const u64* hp = (const u64*)&h1p[k * DSTR];
#pragma unroll
        for (int p = 0; p < 4; p++) acc2[p] = ffma2(hp[p], wd, acc2[p]);
    }
#pragma unroll
    for (int p = 0; p < 4; p++) {
        float2 a = up2(acc2[p]);
        g_AE[(size_t)(NPL + r0 + 2 * p)     * En + tid] = __float2half_rn(tanhf(a.x));
        g_AE[(size_t)(NPL + r0 + 2 * p + 1) * En + tid] = __float2half_rn(tanhf(a.y));
    }
}

// ---------------- K2: relation compress + gate projection (merged, permuted out) ----------------
__global__ void k_rel(const float* __restrict__ rel_table,
                      const float* __restrict__ W, const float* __restrict__ b,
                      const float* __restrict__ b_ih, const float* __restrict__ b_hh) {
    __shared__ float rr[DENT];
    __shared__ float rc[En];
    int row = blockIdx.x, tid = threadIdx.x;
    if (tid < DENT) rr[tid] = rel_table[row * DENT + tid];
    __syncthreads();
    if (tid < En) {
        float s = b[tid];
        for (int k = 0; k < DENT; k++) s += rr[k] * W[k * En + tid];
        rc[tid] = tanhf(s);
    }
    __syncthreads();
    int c = tid;
    int j = c >> 2, g = c & 3;
    int gidx = g * 128 + j;
    float s = b_ih[gidx] + b_hh[gidx];
    for (int k = 0; k < En; k++) s += rc[k] * g_WTrel[k * 512 + c];
    int q = c >> 2;
    int p = (q & ~31) | ((q & 1) << 4) | ((q & 31) >> 1);
    g_relGb[row * 512 + p * 4 + g] = s;
}

// ---------------- K3: entity gather + HMMA compress (2 CTA/SM, overlaid C) ----------------
#define SMC_A 0                            /* 128 * CKSTR = 30720 */
#define SMC_B (128 * CKSTR)                /* 30720 .. 61440 */
#define SMC_TOTAL (2 * 128 * CKSTR)        /* 61440; C staged over A/B after mma */
__global__ __launch_bounds__(512, 2) void k_compress_mma(const int* __restrict__ paths,
                                                         const float* __restrict__ ent_table,
                                                         const float* __restrict__ ec_b) {
    extern __shared__ char sm[];
    __shared__ int spath[128];
    int tid = threadIdx.x, w = tid >> 5, l = tid & 31;
    int wm = w & 3, wn = w >> 2;
    int row0 = blockIdx.x * 128;

    if (tid < 128) spath[tid] = paths[row0 + tid];
    __syncthreads();
    // stage A: gathered entity rows via float4 (row = 25 float4), convert f16
    for (int idx = tid; idx < 128 * 25; idx += 512) {
        int r = idx / 25, k4 = idx - r * 25;
        float4 v = *(const float4*)(ent_table + (size_t)spath[r] * DENT + k4 * 4);
        uint2 u;
        *((__half2*)&u.x) = __floats2half2_rn(v.x, v.y);
        *((__half2*)&u.y) = __floats2half2_rn(v.z, v.w);
        *(uint2*)(sm + SMC_A + r * CKSTR + k4 * 8) = u;
    }
    // zero pad k = 100..111 (24B per row)
    for (int idx = tid; idx < 128 * 3; idx += 512) {
        int r = idx / 3, j = idx - r * 3;
        *(uint2*)(sm + SMC_A + r * CKSTR + 200 + j * 8) = make_uint2(0u, 0u);
    }
    // stage B: ec_W^T f16 (rows of 224B = 28 uint2)
    for (int idx = tid; idx < 128 * 28; idx += 512) {
        int r = idx / 28, j = idx - r * 28;
        *(uint2*)(sm + SMC_B + r * CKSTR + j * 8) = ((const uint2*)g_Wec)[idx];
    }
    __syncthreads();

    uint32_t base = s2u(sm);
    int g8 = l & 7;
    uint32_t aBase = base + SMC_A + (uint32_t)(wm * 32 + g8 + ((l >> 3) & 1) * 8) * CKSTR
                   + ((l >> 4) & 1) * 16;
    uint32_t bBase = base + SMC_B + (uint32_t)(wn * 32 + g8) * CKSTR + ((l >> 3) & 1) * 16;

    float acc[2][4][4];
#pragma unroll
    for (int mt = 0; mt < 2; mt++)
#pragma unroll
        for (int nt = 0; nt < 4; nt++)
#pragma unroll
            for (int q = 0; q < 4; q++) acc[mt][nt][q] = 0.0f;

#pragma unroll
    for (int kt = 0; kt < 7; kt++) {
        uint32_t a[2][4];
        ldmA(a[0], aBase + kt * 32);
        ldmA(a[1], aBase + 16 * CKSTR + kt * 32);
#pragma unroll
        for (int nt = 0; nt < 4; nt++) {
            uint32_t b[2];
            ldmB(b, bBase + nt * 8 * CKSTR + kt * 32);
            mma16816(acc[0][nt], a[0], b);
            mma16816(acc[1][nt], a[1], b);
        }
    }
    __syncthreads();   // A/B dead; overlay C staging at base

    int tg = l & 3, gg = l >> 2;
#pragma unroll
    for (int mt = 0; mt < 2; mt++) {
        int r = wm * 32 + mt * 16 + gg;
#pragma unroll
        for (int nt = 0; nt < 4; nt++) {
            int cc = wn * 32 + nt * 8 + 2 * tg;
            float b0 = __ldg(ec_b + cc), b1 = __ldg(ec_b + cc + 1);
            *(__half2*)(sm + r * ASTR + cc * 2) =
                __floats2half2_rn(tanha(acc[mt][nt][0] + b0), tanha(acc[mt][nt][1] + b1));
            *(__half2*)(sm + (r + 8) * ASTR + cc * 2) =
                __floats2half2_rn(tanha(acc[mt][nt][2] + b0), tanha(acc[mt][nt][3] + b1));
        }
    }
    __syncthreads();
    for (int it = tid; it < 128 * 16; it += 512) {
        int r = it >> 4, bb = it & 15;
        uint4 v = *(uint4*)(sm + r * ASTR + bb * 16);
        *(uint4*)((char*)g_AE + (size_t)(row0 + r) * 256 + bb * 16) = v;
    }
}

// ---------------- K4: HMMA GEMM  g_G16 = g_AE @ g_Bn^T (permuted fp16 out) ----------------
#define SMG_A 0
#define SMG_B (128 * ASTR)                /* 34816 */
#define SMG_TOTAL (SMG_B + 256 * ASTR)    /* 104448 */
__global__ __launch_bounds__(512, 1) void k_gemm_mma() {
    extern __shared__ char sm[];
    int tid = threadIdx.x, w = tid >> 5, l = tid & 31;
    int wm = w & 3, wn = w >> 2;
    int row0 = blockIdx.x * 128;
    int n0b  = blockIdx.y * 256;

    const uint4* Ag = (const uint4*)g_AE;
    for (int idx = tid; idx < 128 * 16; idx += 512) {
        int r = idx >> 4, c4 = idx & 15;
        *(uint4*)(sm + SMG_A + r * ASTR + c4 * 16) = Ag[(size_t)(row0 + r) * 16 + c4];
    }
    const uint4* Bg = (const uint4*)g_Bn;
    for (int idx = tid; idx < 256 * 16; idx += 512) {
        int n = idx >> 4, c4 = idx & 15;
        *(uint4*)(sm + SMG_B + n * ASTR + c4 * 16) = Bg[(size_t)(n0b + n) * 16 + c4];
    }
    __syncthreads();

    uint32_t base = s2u(sm);
    int g8 = l & 7;
    uint32_t aBase = base + SMG_A + (uint32_t)(wm * 32 + g8 + ((l >> 3) & 1) * 8) * ASTR
                   + ((l >> 4) & 1) * 16;
    uint32_t bBase = base + SMG_B + (uint32_t)(wn * 64 + g8) * ASTR + ((l >> 3) & 1) * 16;

    float acc[2][8][4];
#pragma unroll
    for (int mt = 0; mt < 2; mt++)
#pragma unroll
        for (int nt = 0; nt < 8; nt++)
#pragma unroll
            for (int q = 0; q < 4; q++) acc[mt][nt][q] = 0.0f;

#pragma unroll
    for (int kt = 0; kt < 8; kt++) {
        uint32_t a[2][4];
        ldmA(a[0], aBase + kt * 32);
        ldmA(a[1], aBase + 16 * ASTR + kt * 32);
#pragma unroll
        for (int nt = 0; nt < 8; nt++) {
            uint32_t b[2];
            ldmB(b, bBase + nt * 8 * ASTR + kt * 32);
            mma16816(acc[0][nt], a[0], b);
            mma16816(acc[1][nt], a[1], b);
        }
    }
    __syncthreads();

    int tg = l & 3, gg = l >> 2;
#pragma unroll
    for (int mt = 0; mt < 2; mt++) {
        int r = wm * 32 + mt * 16 + gg;
#pragma unroll
        for (int nt = 0; nt < 8; nt++) {
            int qg = wn * 16 + nt * 2 + (tg >> 1);
            int pl = (qg & ~31) | ((qg & 1) << 4) | ((qg & 31) >> 1);
            *(__half2*)(sm + r * CSTR + pl * 8 + (tg & 1) * 4) =
                __floats2half2_rn(acc[mt][nt][0], acc[mt][nt][1]);
            *(__half2*)(sm + (r + 8) * CSTR + pl * 8 + (tg & 1) * 4) =
                __floats2half2_rn(acc[mt][nt][2], acc[mt][nt][3]);
        }
    }
    __syncthreads();
    for (int it = tid; it < 128 * 32; it += 512) {
        int r = it >> 5, bb = it & 31;
        uint4 v = *(uint4*)(sm + r * CSTR + bb * 16);
        *(uint4*)((char*)g_G16 + (size_t)(row0 + r) * 1024 + (size_t)n0b * 2 + bb * 16) = v;
    }
}

// ---------------- K5: HMMA LSTM + fused MLP ----------------
#define SML_A0 0
#define SML_A1 (64 * ASTR)
#define SML_B  (2 * 64 * ASTR)
#define SML_W1 SML_B
#define SML_PART (SML_B + 512 * ASTR)
#define SML_TOTAL (SML_PART + 2048)
__global__ __launch_bounds__(512, 1) void k_lstm_mma(const int* __restrict__ edges,
                                                     const float* __restrict__ mlp_W1,
                                                     const float* __restrict__ mlp_b1,
                                                     const float* __restrict__ mlp_W2,
                                                     const float* __restrict__ mlp_b2,
                                                     float* __restrict__ scores_out) {
    extern __shared__ char sm[];
    int tid = threadIdx.x, w = tid >> 5, l = tid & 31;
    int wm = w & 3, wn = w >> 2;
    int n0 = blockIdx.x * 64;
    int g8 = l & 7, tg = l & 3, gg = l >> 2;
    int odd = tg & 1;
    int par = tg >> 1;

    const uint4* Bg = (const uint4*)g_Bh;
    for (int idx = tid; idx < 512 * 16; idx += 512) {
        int n = idx >> 4, c4 = idx & 15;
        *(uint4*)(sm + SML_B + n * ASTR + c4 * 16) = Bg[(size_t)n * 16 + c4];
    }
    __syncthreads();

    uint32_t base = s2u(sm);
    uint32_t aLane = (uint32_t)(wm * 16 + g8 + ((l >> 3) & 1) * 8) * ASTR + ((l >> 4) & 1) * 16;
    uint32_t bBase = base + SML_B + (uint32_t)(wn * 128 + g8) * ASTR + ((l >> 3) & 1) * 16;

    int r_loc = wm * 16 + gg + odd * 8;
    int seq = n0 + r_loc;
    int bIdx = seq / Pn;

    float cst[16];
#pragma unroll
    for (int q = 0; q < 16; q++) cst[q] = 0.0f;

    for (int t = 0; t < Tn; t++) {
        uint32_t aRd = base + ((t & 1) ? SML_A0 : SML_A1) + aLane;
        char* hWr = sm + ((t & 1) ? SML_A1 : SML_A0);
        int rowG = (t == 0) ? NPL + bIdx
                 : (t == 4) ? NPL + Bsz + bIdx
                 : seq * Ln + (t - 1);
        int e = (t < Ln) ? edges[seq * Ln + t] : 0;
        const uint4* gp = (const uint4*)((const char*)g_G16 + (size_t)rowG * 1024
                                         + (size_t)(wn * 32 + par * 16) * 8);
        const float4* rp = (const float4*)(g_relGb + (size_t)e * 512
                                           + (wn * 32 + par * 16) * 4);

#pragma unroll
        for (int half = 0; half < 2; half++) {
            uint4 gu[4];
#pragma unroll
            for (int k2 = 0; k2 < 4; k2++) gu[k2] = gp[half * 4 + k2];

            float acc[8][4];
#pragma unroll
            for (int nt = 0; nt < 8; nt++)
#pragma unroll
                for (int q = 0; q < 4; q++) acc[nt][q] = 0.0f;
            if (t > 0) {
#pragma unroll
                for (int kt = 0; kt < 8; kt++) {
                    uint32_t a[4];
                    ldmA(a, aRd + kt * 32);
#pragma unroll
                    for (int ntl = 0; ntl < 8; ntl++) {
                        uint32_t b[2];
                        ldmB(b, bBase + (half * 8 + ntl) * 8 * ASTR + kt * 32);
                        mma16816(acc[ntl], a, b);
                    }
                }
            }
#pragma unroll
            for (int ntl = 0; ntl < 8; ntl++) {
                int nt = half * 8 + ntl;
                float d0 = acc[ntl][0], d1 = acc[ntl][1];
                float d2 = acc[ntl][2], d3 = acc[ntl][3];
                float x0 = __shfl_xor_sync(0xffffffffu, d0, 1);
                float x1 = __shfl_xor_sync(0xffffffffu, d1, 1);
                float x2 = __shfl_xor_sync(0xffffffffu, d2, 1);
                float x3 = __shfl_xor_sync(0xffffffffu, d3, 1);
                float gi = odd ? x2 : d0;
                float gf = odd ? x3 : d1;
                float gG = odd ? d2 : x0;
                float gO = odd ? d3 : x1;
                __half2 hif = ((const __half2*)&gu[ntl >> 1])[(ntl & 1) * 2 + 0];
                __half2 hgo = ((const __half2*)&gu[ntl >> 1])[(ntl & 1) * 2 + 1];
                float2 fif = __half22float2(hif);
                float2 fgo = __half22float2(hgo);
                float4 r4 = rp[nt];
                gi += fif.x + r4.x;
                gf += fif.y + r4.y;
                gG += fgo.x + r4.z;
                gO += fgo.y + r4.w;
                cst[nt] = siga(gf) * cst[nt] + siga(gi) * tanha(gG);
                float hv = siga(gO) * tanha(cst[nt]);
                int q = wn * 32 + nt * 2 + par;
                *(__half*)(hWr + r_loc * ASTR + q * 2) = __float2half_rn(hv);
            }
        }
        __syncthreads();
    }

    // ---- fused MLP: final h in buffer A0 ----
    float* sW1 = (float*)(sm + SML_W1);
    for (int idx = tid; idx < 128 * 128; idx += 512) sW1[idx] = mlp_W1[idx];
    __syncthreads();

    int m = tid & 63, jb = (tid >> 6) * 16;
    u64 m1[8];
#pragma unroll
    for (int p = 0; p < 8; p++) m1[p] = pack2(mlp_b1[jb + 2 * p], mlp_b1[jb + 2 * p + 1]);
    const __half* hrow = (const __half*)(sm + SML_A0 + m * ASTR);
#pragma unroll 4
    for (int k = 0; k < 128; k++) {
        u64 hd = dup2(__half2float(hrow[k]));
        const u64* wp = (const u64*)&sW1[k * 128 + jb];
#pragma unroll
        for (int p = 0; p < 8; p++) m1[p] = ffma2(wp[p], hd, m1[p]);
    }
    float v = 0.0f;
#pragma unroll
    for (int p = 0; p < 8; p++) {
        float2 a = up2(m1[p]);
        v += fmaxf(a.x, 0.0f) * mlp_W2[jb + 2 * p]
           + fmaxf(a.y, 0.0f) * mlp_W2[jb + 2 * p + 1];
    }
    float* part = (float*)(sm + SML_PART);
    part[m * 8 + (tid >> 6)] = v;
    __syncthreads();
    if (tid < 64) {
        float s = mlp_b2[0];
#pragma unroll
        for (int p = 0; p < 8; p++) s += part[tid * 8 + p];
        scores_out[n0 + tid] = s;
    }
}

// ---------------- K7: logsumexp + BCE ----------------
__global__ void k_final(const float* __restrict__ label, float* __restrict__ out) {
    __shared__ float red[Bsz];
    int b = threadIdx.x;
    const float* sc = out + 1 + Bsz + b * Pn;
    float mx = -1e30f;
#pragma unroll
    for (int p = 0; p < Pn; p++) mx = fmaxf(mx, sc[p] * 0.5f);
    float s = 0.0f;
#pragma unroll
    for (int p = 0; p < Pn; p++) s += expf(sc[p] * 0.5f - mx);
    float lse = mx + logf(s);
    float pr = 1.0f / (1.0f + expf(-lse));
    out[1 + b] = pr;
    float pc = fminf(fmaxf(pr, 1e-7f), 1.0f - 1e-7f);
    float lb = label[b];
    red[b] = -(lb * logf(pc) + (1.0f - lb) * logf(1.0f - pc));
    __syncthreads();
    for (int st = Bsz / 2; st > 0; st >>= 1) {
        if (b < st) red[b] += red[b + st];
        __syncthreads();
    }
    if (b == 0) out[0] = red[0] / (float)Bsz;
}

// ---------------- launch ----------------
extern "C" void kernel_launch(void* const* d_in, const int* in_sizes, int n_in,
                              void* d_out, int out_size) {
    const int*   item1     = (const int*)d_in[0];
    const int*   item2     = (const int*)d_in[1];
    const int*   paths     = (const int*)d_in[2];
    const int*   edges     = (const int*)d_in[3];
    const float* label     = (const float*)d_in[4];
    const float* doc_table = (const float*)d_in[5];
    const float* ent_table = (const float*)d_in[6];
    const float* rel_table = (const float*)d_in[7];
    const float* nc_W1 = (const float*)d_in[8];
    const float* nc_b1 = (const float*)d_in[9];
    const float* nc_W2 = (const float*)d_in[10];
    const float* nc_b2 = (const float*)d_in[11];
    const float* ec_W  = (const float*)d_in[12];
    const float* ec_b  = (const float*)d_in[13];
    const float* rc_W  = (const float*)d_in[14];
    const float* rc_b  = (const float*)d_in[15];
    const float* W_ih  = (const float*)d_in[16];
    const float* W_hh  = (const float*)d_in[17];
    const float* b_ih  = (const float*)d_in[18];
    const float* b_hh  = (const float*)d_in[19];
    const float* mlp_W1 = (const float*)d_in[20];
    const float* mlp_b1 = (const float*)d_in[21];
    const float* mlp_W2 = (const float*)d_in[22];
    const float* mlp_b2 = (const float*)d_in[23];
    float* out = (float*)d_out;

    cudaFuncSetAttribute(k_compress_mma, cudaFuncAttributeMaxDynamicSharedMemorySize, SMC_TOTAL);
    cudaFuncSetAttribute(k_gemm_mma, cudaFuncAttributeMaxDynamicSharedMemorySize, SMG_TOTAL);
    cudaFuncSetAttribute(k_lstm_mma, cudaFuncAttributeMaxDynamicSharedMemorySize, SML_TOTAL);

    k_transpose<<<(512 * 128 + 511) / 512, 512>>>(W_ih, W_hh, ec_W);
    k_news<<<2 * Bsz / 8, 128>>>(item1, item2, doc_table, nc_W1, nc_b1, nc_W2, nc_b2);
    k_rel<<<NREL, 512>>>(rel_table, rc_W, rc_b, b_ih, b_hh);
    k_compress_mma<<<NPL / 128, 512, SMC_TOTAL>>>(paths, ent_table, ec_b);
    k_gemm_mma<<<dim3(MTOT / 128, 2), 512, SMG_TOTAL>>>();
    k_lstm_mma<<<Nseq / 64, 512, SML_TOTAL>>>(edges, mlp_W1, mlp_b1, mlp_W2, mlp_b2,
                                              out + 1 + Bsz);
    k_final<<<1, Bsz>>>(label, out);
}